// round 2
// baseline (speedup 1.0000x reference)
#include <cuda_runtime.h>
#include <math.h>

#define NB 2
#define NH 16
#define HD 64
#define SQ 2048
#define EM 1024

// Scratch (device globals; no runtime allocation allowed)
__device__ float g_Q[(size_t)NB*NH*SQ*HD];
__device__ float g_K[(size_t)NB*NH*SQ*HD];
__device__ float g_V[(size_t)NB*NH*SQ*HD];
__device__ float g_ctx[(size_t)NB*SQ*EM];

// ---------------------------------------------------------------------------
// Tiled GEMM: C = A[M,K] @ W[K,N] + bias[N]
// mode 0: C stored plain [M,N]
// mode 1: C stored as [B, H, S, D] with m=(b,s), n=(h,d)  (S=2048, D=64)
// Block tile 128x64, K-tile 16, 256 threads, 8x4 micro-tile.
// Per k-step per warp: 3x LDS.128 per 32 FFMA -> FMA-bound (not crossbar).
// ---------------------------------------------------------------------------
__global__ __launch_bounds__(256)
void gemm128(const float* __restrict__ A, const float* __restrict__ W,
             const float* __restrict__ bias, float* __restrict__ C,
             int M, int N, int K, int mode)
{
    __shared__ float As[16][128];  // [k][m] (transposed)
    __shared__ float Bs[16][64];   // [k][n]
    const int m0 = blockIdx.y * 128;
    const int n0 = blockIdx.x * 64;
    const int tid = threadIdx.x;
    const int tx = tid & 15, ty = tid >> 4;    // tx: 4 n-cols, ty: 8 m-rows
    const int lk = tid >> 4, lnq = tid & 15;   // B-load mapping

    float c[8][4] = {};
    for (int k0 = 0; k0 < K; k0 += 16) {
        // A tile: 128 rows x 16 k  = 512 float4, 2 per thread
#pragma unroll
        for (int i = 0; i < 2; i++) {
            int lin = tid + i * 256;          // 0..511
            int row = lin >> 2, c4 = lin & 3;
            float4 av = *(const float4*)(A + (size_t)(m0 + row) * K + k0 + c4 * 4);
            As[c4*4+0][row] = av.x;
            As[c4*4+1][row] = av.y;
            As[c4*4+2][row] = av.z;
            As[c4*4+3][row] = av.w;
        }
        // B tile: 16 k x 64 n = 256 float4, 1 per thread
        *(float4*)&Bs[lk][lnq*4] =
            *(const float4*)(W + (size_t)(k0 + lk) * N + n0 + lnq * 4);
        __syncthreads();
#pragma unroll
        for (int kk = 0; kk < 16; kk++) {
            float4 a0 = *(const float4*)&As[kk][ty*8];
            float4 a1 = *(const float4*)&As[kk][ty*8 + 4];
            float4 b4 = *(const float4*)&Bs[kk][tx*4];
            float ar[8] = {a0.x, a0.y, a0.z, a0.w, a1.x, a1.y, a1.z, a1.w};
            float br[4] = {b4.x, b4.y, b4.z, b4.w};
#pragma unroll
            for (int i = 0; i < 8; i++)
#pragma unroll
                for (int j = 0; j < 4; j++)
                    c[i][j] = fmaf(ar[i], br[j], c[i][j]);
        }
        __syncthreads();
    }

    float4 bb4 = *(const float4*)(bias + n0 + tx*4);
    float br[4] = {bb4.x, bb4.y, bb4.z, bb4.w};
#pragma unroll
    for (int i = 0; i < 8; i++) {
        int m = m0 + ty*8 + i;
        float4 v;
        v.x = c[i][0] + br[0];
        v.y = c[i][1] + br[1];
        v.z = c[i][2] + br[2];
        v.w = c[i][3] + br[3];
        if (mode == 0) {
            *(float4*)(C + (size_t)m * N + n0 + tx*4) = v;
        } else {
            int bbi = m >> 11;          // S = 2048
            int s   = m & 2047;
            int h   = n0 >> 6;          // D = 64, n-tile == one head
            *(float4*)(C + (((size_t)(bbi*NH + h) * SQ + s) * HD) + tx*4) = v;
        }
    }
}

// ---------------------------------------------------------------------------
// L2-normalize rows of length 64 in place: p /= (||p|| + 1e-8). One warp/row.
// ---------------------------------------------------------------------------
__global__ void l2norm_rows(float* __restrict__ P, int rows)
{
    int w = (blockIdx.x * blockDim.x + threadIdx.x) >> 5;
    int lane = threadIdx.x & 31;
    if (w >= rows) return;
    float* p = P + (size_t)w * HD;
    float v0 = p[lane], v1 = p[lane + 32];
    float ss = v0*v0 + v1*v1;
#pragma unroll
    for (int o = 16; o > 0; o >>= 1)
        ss += __shfl_xor_sync(0xffffffff, ss, o);
    float sc = 1.0f / (sqrtf(ss) + 1e-8f);
    p[lane]      = v0 * sc;
    p[lane + 32] = v1 * sc;
}

// ---------------------------------------------------------------------------
// Yat attention: one block = (b, h, 64-query tile). Loop over 64-key tiles.
// scores = (1+dot)^2 / (0.1 + (1-dot)); sum-normalized (no softmax/max).
// Shared (dynamic, 66,560 B): Qs/Ks/Vs/Ss each 64x65 fp32 (pad for banks).
// ---------------------------------------------------------------------------
__global__ __launch_bounds__(256)
void yat_attn(const float* __restrict__ Q, const float* __restrict__ K,
              const float* __restrict__ V, float* __restrict__ ctx)
{
    extern __shared__ float sh[];
    float* Qs  = sh;            // [64][65]
    float* Ks  = sh + 4160;     // [64][65]
    float* Vs  = sh + 8320;     // [64][65]
    float* Ssh = sh + 12480;    // [64][65]; reused for den reduction at end

    const int q0 = blockIdx.x * 64;
    const int h  = blockIdx.y;
    const int bb = blockIdx.z;
    const size_t hb = ((size_t)bb * NH + h) * SQ;
    const float* Qh = Q + hb * HD;
    const float* Kh = K + hb * HD;
    const float* Vh = V + hb * HD;
    const int tid = threadIdx.x;
    const int tx = tid & 15, ty = tid >> 4;

    // Load Q tile (64 x 64)
#pragma unroll
    for (int i = 0; i < 4; i++) {
        int lin = tid + i * 256;          // 0..1023 float4 slots
        int row = lin >> 4, c4 = lin & 15;
        float4 v = *(const float4*)(Qh + (size_t)(q0 + row) * HD + c4*4);
        Qs[row*65 + c4*4+0] = v.x;
        Qs[row*65 + c4*4+1] = v.y;
        Qs[row*65 + c4*4+2] = v.z;
        Qs[row*65 + c4*4+3] = v.w;
    }

    float o[4][4] = {};
    float denP[4] = {};

    for (int kt = 0; kt < SQ; kt += 64) {
        __syncthreads();   // prior tile's PV done; also covers Q-tile readiness
#pragma unroll
        for (int i = 0; i < 4; i++) {
            int lin = tid + i * 256;
            int row = lin >> 4, c4 = lin & 15;
            float4 kv = *(const float4*)(Kh + (size_t)(kt + row) * HD + c4*4);
            float4 vv = *(const float4*)(Vh + (size_t)(kt + row) * HD + c4*4);
            Ks[row*65 + c4*4+0] = kv.x; Ks[row*65 + c4*4+1] = kv.y;
            Ks[row*65 + c4*4+2] = kv.z; Ks[row*65 + c4*4+3] = kv.w;
            Vs[row*65 + c4*4+0] = vv.x; Vs[row*65 + c4*4+1] = vv.y;
            Vs[row*65 + c4*4+2] = vv.z; Vs[row*65 + c4*4+3] = vv.w;
        }
        __syncthreads();

        // QK^T (dot over d)
        float s[4][4] = {};
#pragma unroll
        for (int kk = 0; kk < 64; kk++) {
            float a[4], b[4];
#pragma unroll
            for (int i = 0; i < 4; i++) a[i] = Qs[(ty*4 + i)*65 + kk];
#pragma unroll
            for (int j = 0; j < 4; j++) b[j] = Ks[(tx + 16*j)*65 + kk];
#pragma unroll
            for (int i = 0; i < 4; i++)
#pragma unroll
                for (int j = 0; j < 4; j++)
                    s[i][j] = fmaf(a[i], b[j], s[i][j]);
        }

        // Yat transform + write scores + accumulate denominator partials
#pragma unroll
        for (int i = 0; i < 4; i++) {
#pragma unroll
            for (int j = 0; j < 4; j++) {
                float dot = s[i][j];
                float t1 = 1.0f + dot;
                float sc = t1 * t1 / (0.1f + (1.0f - dot));
                denP[i] += sc;
                Ssh[(ty*4 + i)*65 + (tx + 16*j)] = sc;
            }
        }
        __syncthreads();

        // P @ V (sum over k)
#pragma unroll
        for (int kk = 0; kk < 64; kk++) {
            float a[4], b[4];
#pragma unroll
            for (int i = 0; i < 4; i++) a[i] = Ssh[(ty*4 + i)*65 + kk];
#pragma unroll
            for (int j = 0; j < 4; j++) b[j] = Vs[kk*65 + (tx + 16*j)];
#pragma unroll
            for (int i = 0; i < 4; i++)
#pragma unroll
                for (int j = 0; j < 4; j++)
                    o[i][j] = fmaf(a[i], b[j], o[i][j]);
        }
    }
    __syncthreads();

    // Reduce denominator partials across the 16 tx threads per q-row.
    float* denPart = Ssh;  // reuse: [q][16]
#pragma unroll
    for (int i = 0; i < 4; i++) denPart[(ty*4 + i)*16 + tx] = denP[i];
    __syncthreads();

#pragma unroll
    for (int i = 0; i < 4; i++) {
        float sum = 0.0f;
#pragma unroll
        for (int t = 0; t < 16; t++) sum += denPart[(ty*4 + i)*16 + t];
        float inv = 1.0f / (sum + 1e-6f);
        int q = q0 + ty*4 + i;
        float* dst = ctx + ((size_t)bb * SQ + q) * EM + h * HD;
#pragma unroll
        for (int j = 0; j < 4; j++)
            dst[tx + 16*j] = o[i][j] * inv;
    }
}

// ---------------------------------------------------------------------------
extern "C" void kernel_launch(void* const* d_in, const int* in_sizes, int n_in,
                              void* d_out, int out_size)
{
    const float* x  = (const float*)d_in[0];
    const float* Wq = (const float*)d_in[1];
    const float* bq = (const float*)d_in[2];
    const float* Wk = (const float*)d_in[3];
    const float* bk = (const float*)d_in[4];
    const float* Wv = (const float*)d_in[5];
    const float* bv = (const float*)d_in[6];
    const float* Wo = (const float*)d_in[7];
    const float* bo = (const float*)d_in[8];
    float* out = (float*)d_out;

    float *dQ, *dK, *dV, *dC;
    cudaGetSymbolAddress((void**)&dQ, g_Q);
    cudaGetSymbolAddress((void**)&dK, g_K);
    cudaGetSymbolAddress((void**)&dV, g_V);
    cudaGetSymbolAddress((void**)&dC, g_ctx);

    const int M = NB * SQ, N = EM, K = EM;
    dim3 gg(N / 64, M / 128);

    gemm128<<<gg, 256>>>(x, Wq, bq, dQ, M, N, K, 1);
    gemm128<<<gg, 256>>>(x, Wk, bk, dK, M, N, K, 1);
    gemm128<<<gg, 256>>>(x, Wv, bv, dV, M, N, K, 1);

    int rows = NB * NH * SQ;
    int nthreads = rows * 32;
    l2norm_rows<<<(nthreads + 255) / 256, 256>>>(dQ, rows);
    l2norm_rows<<<(nthreads + 255) / 256, 256>>>(dK, rows);

    size_t attn_smem = (size_t)4 * 4160 * sizeof(float);  // 66,560 B
    cudaFuncSetAttribute(yat_attn, cudaFuncAttributeMaxDynamicSharedMemorySize,
                         (int)attn_smem);
    yat_attn<<<dim3(SQ / 64, NH, NB), 256, attn_smem>>>(dQ, dK, dV, dC);

    gemm128<<<gg, 256>>>(dC, Wo, bo, out, M, N, K, 0);
}

// round 3
// speedup vs baseline: 2.6742x; 2.6742x over previous
#include <cuda_runtime.h>
#include <cuda_fp16.h>
#include <math.h>

#define NB 2
#define NH 16
#define HD 64
#define SQ 2048
#define EM 1024

// Scratch (device globals; runtime allocation is forbidden)
__device__ __align__(256) __half g_Xh[(size_t)NB*SQ*EM];
__device__ __align__(256) __half g_Qh[(size_t)NB*NH*SQ*HD];
__device__ __align__(256) __half g_Kh[(size_t)NB*NH*SQ*HD];
__device__ __align__(256) __half g_Vh[(size_t)NB*NH*SQ*HD];
__device__ __align__(256) __half g_Ch[(size_t)NB*SQ*EM];

// ---------------------------------------------------------------------------
__device__ __forceinline__ void mma16816(float c[4], const unsigned a[4],
                                         unsigned b0, unsigned b1)
{
    asm volatile(
        "mma.sync.aligned.m16n8k16.row.col.f32.f16.f16.f32 "
        "{%0,%1,%2,%3}, {%4,%5,%6,%7}, {%8,%9}, {%0,%1,%2,%3};\n"
        : "+f"(c[0]), "+f"(c[1]), "+f"(c[2]), "+f"(c[3])
        : "r"(a[0]), "r"(a[1]), "r"(a[2]), "r"(a[3]), "r"(b0), "r"(b1));
}

__device__ __forceinline__ unsigned packh2(float x, float y)
{
    __half2 h = __floats2half2_rn(x, y);
    return *(unsigned*)&h;
}

// ---------------------------------------------------------------------------
// x fp32 -> fp16
// ---------------------------------------------------------------------------
__global__ void f2h(const float* __restrict__ src, __half* __restrict__ dst, int n4)
{
    int i = blockIdx.x * blockDim.x + threadIdx.x;
    if (i >= n4) return;
    float4 v = ((const float4*)src)[i];
    ((__half2*)dst)[i*2]   = __floats2half2_rn(v.x, v.y);
    ((__half2*)dst)[i*2+1] = __floats2half2_rn(v.z, v.w);
}

// ---------------------------------------------------------------------------
// Tensor-core GEMM: C = A(fp16)[M,K] @ W(fp32->fp16)[K,N] + bias
// mode 0: C fp32 plain [M,N] (final output)
// mode 1: C fp16 scattered to [B, H, S, D] (projections)
// Block 128x128, k-chunk 32, 8 warps (2m x 4n), warp tile 64x32.
// ---------------------------------------------------------------------------
__global__ __launch_bounds__(256)
void gemm_h(const __half* __restrict__ A, const float* __restrict__ W,
            const float* __restrict__ bias, void* __restrict__ Cout,
            int M, int N, int K, int mode)
{
    __shared__ __half As[128][40];   // [m][k], pad 8 -> conflict-free frags
    __shared__ __half Bs[128][40];   // [n][k] (transposed on load)
    const int m0 = blockIdx.y * 128, n0 = blockIdx.x * 128;
    const int tid = threadIdx.x;
    const int wid = tid >> 5, lane = tid & 31;
    const int g = lane >> 2, tig = lane & 3;
    const int wm = (wid >> 2) * 64, wn = (wid & 3) * 32;

    float c[4][4][4];
#pragma unroll
    for (int i = 0; i < 4; i++)
#pragma unroll
        for (int j = 0; j < 4; j++)
#pragma unroll
            for (int r = 0; r < 4; r++) c[i][j][r] = 0.0f;

    for (int k0 = 0; k0 < K; k0 += 32) {
        // A tile: 128 x 32 halves, uint4 = 8 halves
#pragma unroll
        for (int it = 0; it < 2; it++) {
            int lin = tid + it * 256;
            int row = lin >> 2, c8 = (lin & 3) * 8;
            *(uint4*)&As[row][c8] =
                *(const uint4*)(A + (size_t)(m0 + row) * K + k0 + c8);
        }
        // W tile: 32 x 128 fp32, transpose into Bs[n][k] fp16
#pragma unroll
        for (int it = 0; it < 4; it++) {
            int lin = tid + it * 256;
            int kr = lin >> 5, c4 = (lin & 31) * 4;
            float4 v = *(const float4*)(W + (size_t)(k0 + kr) * N + n0 + c4);
            Bs[c4+0][kr] = __float2half_rn(v.x);
            Bs[c4+1][kr] = __float2half_rn(v.y);
            Bs[c4+2][kr] = __float2half_rn(v.z);
            Bs[c4+3][kr] = __float2half_rn(v.w);
        }
        __syncthreads();
#pragma unroll
        for (int kk = 0; kk < 32; kk += 16) {
            unsigned a[4][4], b[4][2];
#pragma unroll
            for (int i = 0; i < 4; i++) {
                int r = wm + i * 16 + g;
                a[i][0] = *(const unsigned*)&As[r][kk + tig*2];
                a[i][1] = *(const unsigned*)&As[r + 8][kk + tig*2];
                a[i][2] = *(const unsigned*)&As[r][kk + tig*2 + 8];
                a[i][3] = *(const unsigned*)&As[r + 8][kk + tig*2 + 8];
            }
#pragma unroll
            for (int j = 0; j < 4; j++) {
                int n = wn + j * 8 + g;
                b[j][0] = *(const unsigned*)&Bs[n][kk + tig*2];
                b[j][1] = *(const unsigned*)&Bs[n][kk + tig*2 + 8];
            }
#pragma unroll
            for (int i = 0; i < 4; i++)
#pragma unroll
                for (int j = 0; j < 4; j++)
                    mma16816(c[i][j], a[i], b[j][0], b[j][1]);
        }
        __syncthreads();
    }

    // Epilogue
#pragma unroll
    for (int j = 0; j < 4; j++) {
        int col = n0 + wn + j * 8 + tig * 2;
        float b0 = bias[col], b1 = bias[col + 1];
#pragma unroll
        for (int i = 0; i < 4; i++) {
            int r0 = m0 + wm + i * 16 + g;
            int r1 = r0 + 8;
            float v00 = c[i][j][0] + b0, v01 = c[i][j][1] + b1;
            float v10 = c[i][j][2] + b0, v11 = c[i][j][3] + b1;
            if (mode == 0) {
                float2* o0 = (float2*)((float*)Cout + (size_t)r0 * N + col);
                float2* o1 = (float2*)((float*)Cout + (size_t)r1 * N + col);
                *o0 = make_float2(v00, v01);
                *o1 = make_float2(v10, v11);
            } else {
                __half* oh = (__half*)Cout;
                int hh = (n0 + wn + j * 8) >> 6;  // head index (D=64)
                int d  = col & 63;
                int bb0 = r0 >> 11, s0 = r0 & 2047;
                int bb1 = r1 >> 11, s1 = r1 & 2047;
                *(__half2*)(oh + (((size_t)(bb0*NH + hh) * SQ + s0) * HD) + d) =
                    __floats2half2_rn(v00, v01);
                *(__half2*)(oh + (((size_t)(bb1*NH + hh) * SQ + s1) * HD) + d) =
                    __floats2half2_rn(v10, v11);
            }
        }
    }
}

// ---------------------------------------------------------------------------
// L2-normalize fp16 rows of length 64 in place (fp32 math). One warp/row.
// ---------------------------------------------------------------------------
__global__ void l2norm_h(__half* __restrict__ P, int rows)
{
    int w = (blockIdx.x * blockDim.x + threadIdx.x) >> 5;
    int lane = threadIdx.x & 31;
    if (w >= rows) return;
    __half2* p = (__half2*)(P + (size_t)w * HD);
    __half2 hv = p[lane];
    float2 f = __half22float2(hv);
    float ss = f.x * f.x + f.y * f.y;
#pragma unroll
    for (int o = 16; o > 0; o >>= 1)
        ss += __shfl_xor_sync(0xffffffff, ss, o);
    float sc = 1.0f / (sqrtf(ss) + 1e-8f);
    p[lane] = __floats2half2_rn(f.x * sc, f.y * sc);
}

// ---------------------------------------------------------------------------
// Tensor-core Yat attention. Block = (b, h, 64 queries), 4 warps (16 q each).
// QK^T via mma (fp16 in, fp32 out) -> yat transform fp32 -> P fp16 in regs
// (C-frag == A-frag layout) -> PV via mma -> divide by fp32 row sum.
// smem: Qs/Ks [row][d] and Vs [d][row], all padded to 72 (conflict-free).
// ---------------------------------------------------------------------------
__global__ __launch_bounds__(128)
void yat_attn_h(const __half* __restrict__ Q, const __half* __restrict__ K,
                const __half* __restrict__ V, __half* __restrict__ ctx)
{
    __shared__ __half Qs[64][72];
    __shared__ __half Ks[64][72];
    __shared__ __half Vs[64][72];

    const int q0 = blockIdx.x * 64;
    const int h  = blockIdx.y;
    const int bb = blockIdx.z;
    const size_t base = ((size_t)bb * NH + h) * SQ * HD;
    const int tid = threadIdx.x;
    const int wid = tid >> 5, lane = tid & 31;
    const int g = lane >> 2, tig = lane & 3;
    const int qr = wid * 16;

    // Load Q tile (64 x 64 halves)
#pragma unroll
    for (int it = 0; it < 4; it++) {
        int lin = tid + it * 128;
        int row = lin >> 3, c8 = (lin & 7) * 8;
        *(uint4*)&Qs[row][c8] = *(const uint4*)(Q + base + (size_t)(q0 + row) * HD + c8);
    }
    __syncthreads();

    // Q fragments (constant across key tiles)
    unsigned qa[4][4];
#pragma unroll
    for (int t = 0; t < 4; t++) {
        qa[t][0] = *(const unsigned*)&Qs[qr + g][t*16 + tig*2];
        qa[t][1] = *(const unsigned*)&Qs[qr + g + 8][t*16 + tig*2];
        qa[t][2] = *(const unsigned*)&Qs[qr + g][t*16 + tig*2 + 8];
        qa[t][3] = *(const unsigned*)&Qs[qr + g + 8][t*16 + tig*2 + 8];
    }

    float o[8][4];
#pragma unroll
    for (int j = 0; j < 8; j++)
#pragma unroll
        for (int r = 0; r < 4; r++) o[j][r] = 0.0f;
    float den0 = 0.0f, den1 = 0.0f;

    for (int kt = 0; kt < SQ; kt += 64) {
        __syncthreads();
#pragma unroll
        for (int it = 0; it < 4; it++) {
            int lin = tid + it * 128;
            int row = lin >> 3, c8 = (lin & 7) * 8;
            *(uint4*)&Ks[row][c8] =
                *(const uint4*)(K + base + (size_t)(kt + row) * HD + c8);
            uint4 vv = *(const uint4*)(V + base + (size_t)(kt + row) * HD + c8);
            const __half* hv = (const __half*)&vv;
#pragma unroll
            for (int u = 0; u < 8; u++) Vs[c8 + u][row] = hv[u];
        }
        __syncthreads();

        // QK^T: m16 (queries) x n64 (keys) x k64 (d)
        float sc[8][4];
#pragma unroll
        for (int j = 0; j < 8; j++)
#pragma unroll
            for (int r = 0; r < 4; r++) sc[j][r] = 0.0f;
#pragma unroll
        for (int t = 0; t < 4; t++)
#pragma unroll
            for (int j = 0; j < 8; j++) {
                unsigned b0 = *(const unsigned*)&Ks[j*8 + g][t*16 + tig*2];
                unsigned b1 = *(const unsigned*)&Ks[j*8 + g][t*16 + tig*2 + 8];
                mma16816(sc[j], qa[t], b0, b1);
            }

        // Yat transform + denominator partials
#pragma unroll
        for (int j = 0; j < 8; j++) {
#pragma unroll
            for (int r = 0; r < 4; r++) {
                float dot = sc[j][r];
                float t1 = 1.0f + dot;
                sc[j][r] = t1 * t1 / (0.1f + (1.0f - dot));
            }
            den0 += sc[j][0] + sc[j][1];
            den1 += sc[j][2] + sc[j][3];
        }

        // P fp16 A-fragments straight from C-fragment registers
        unsigned ph[4][4];
#pragma unroll
        for (int t = 0; t < 4; t++) {
            ph[t][0] = packh2(sc[2*t][0],   sc[2*t][1]);
            ph[t][1] = packh2(sc[2*t][2],   sc[2*t][3]);
            ph[t][2] = packh2(sc[2*t+1][0], sc[2*t+1][1]);
            ph[t][3] = packh2(sc[2*t+1][2], sc[2*t+1][3]);
        }

        // P @ V: m16 x n64 (d) x k64 (keys)
#pragma unroll
        for (int t = 0; t < 4; t++)
#pragma unroll
            for (int j = 0; j < 8; j++) {
                unsigned b0 = *(const unsigned*)&Vs[j*8 + g][t*16 + tig*2];
                unsigned b1 = *(const unsigned*)&Vs[j*8 + g][t*16 + tig*2 + 8];
                mma16816(o[j], ph[t], b0, b1);
            }
    }

    // Reduce denominators across the 4 tig lanes (butterfly -> all lanes hold)
    den0 += __shfl_xor_sync(0xffffffff, den0, 1);
    den0 += __shfl_xor_sync(0xffffffff, den0, 2);
    den1 += __shfl_xor_sync(0xffffffff, den1, 1);
    den1 += __shfl_xor_sync(0xffffffff, den1, 2);
    float inv0 = 1.0f / (den0 + 1e-6f);
    float inv1 = 1.0f / (den1 + 1e-6f);

    // Write ctx [b][s][h*64+d] fp16
    const size_t obase = (size_t)bb * SQ * EM + (size_t)h * HD;
    int r0 = q0 + qr + g, r1 = r0 + 8;
#pragma unroll
    for (int j = 0; j < 8; j++) {
        int col = j * 8 + tig * 2;
        *(__half2*)(ctx + obase + (size_t)r0 * EM + col) =
            __floats2half2_rn(o[j][0] * inv0, o[j][1] * inv0);
        *(__half2*)(ctx + obase + (size_t)r1 * EM + col) =
            __floats2half2_rn(o[j][2] * inv1, o[j][3] * inv1);
    }
}

// ---------------------------------------------------------------------------
extern "C" void kernel_launch(void* const* d_in, const int* in_sizes, int n_in,
                              void* d_out, int out_size)
{
    const float* x  = (const float*)d_in[0];
    const float* Wq = (const float*)d_in[1];
    const float* bq = (const float*)d_in[2];
    const float* Wk = (const float*)d_in[3];
    const float* bk = (const float*)d_in[4];
    const float* Wv = (const float*)d_in[5];
    const float* bv = (const float*)d_in[6];
    const float* Wo = (const float*)d_in[7];
    const float* bo = (const float*)d_in[8];
    float* out = (float*)d_out;

    __half *dXh, *dQh, *dKh, *dVh, *dCh;
    cudaGetSymbolAddress((void**)&dXh, g_Xh);
    cudaGetSymbolAddress((void**)&dQh, g_Qh);
    cudaGetSymbolAddress((void**)&dKh, g_Kh);
    cudaGetSymbolAddress((void**)&dVh, g_Vh);
    cudaGetSymbolAddress((void**)&dCh, g_Ch);

    const int M = NB * SQ, N = EM, K = EM;

    // x -> fp16
    int n4 = (M * K) / 4;
    f2h<<<(n4 + 255) / 256, 256>>>(x, dXh, n4);

    dim3 gg(N / 128, M / 128);
    gemm_h<<<gg, 256>>>(dXh, Wq, bq, dQh, M, N, K, 1);
    gemm_h<<<gg, 256>>>(dXh, Wk, bk, dKh, M, N, K, 1);
    gemm_h<<<gg, 256>>>(dXh, Wv, bv, dVh, M, N, K, 1);

    int rows = NB * NH * SQ;
    int nthreads = rows * 32;
    l2norm_h<<<(nthreads + 255) / 256, 256>>>(dQh, rows);
    l2norm_h<<<(nthreads + 255) / 256, 256>>>(dKh, rows);

    yat_attn_h<<<dim3(SQ / 64, NH, NB), 128>>>(dQh, dKh, dVh, dCh);

    gemm_h<<<gg, 256>>>(dCh, Wo, bo, out, M, N, K, 0);
}

// round 6
// speedup vs baseline: 5.8967x; 2.2050x over previous
#include <cuda_runtime.h>
#include <cuda_fp16.h>
#include <cstdint>
#include <math.h>

#define NB 2
#define NH 16
#define HD 64
#define SQ 2048
#define EM 1024

// Scratch (device globals; runtime allocation is forbidden)
__device__ __align__(256) __half g_Xh[(size_t)NB*SQ*EM];
__device__ __align__(256) __half g_Wh[(size_t)4*EM*EM];   // Wq,Wk,Wv,Wo fp16
__device__ __align__(256) __half g_Qh[(size_t)NB*NH*SQ*HD];
__device__ __align__(256) __half g_Kh[(size_t)NB*NH*SQ*HD];
__device__ __align__(256) __half g_Vh[(size_t)NB*NH*SQ*HD];
__device__ __align__(256) __half g_Ch[(size_t)NB*SQ*EM];

// ---------------------------------------------------------------------------
__device__ __forceinline__ void mma16816(float c[4], const unsigned a[4],
                                         unsigned b0, unsigned b1)
{
    asm volatile(
        "mma.sync.aligned.m16n8k16.row.col.f32.f16.f16.f32 "
        "{%0,%1,%2,%3}, {%4,%5,%6,%7}, {%8,%9}, {%0,%1,%2,%3};\n"
        : "+f"(c[0]), "+f"(c[1]), "+f"(c[2]), "+f"(c[3])
        : "r"(a[0]), "r"(a[1]), "r"(a[2]), "r"(a[3]), "r"(b0), "r"(b1));
}
__device__ __forceinline__ unsigned packh2(float x, float y)
{
    __half2 h = __floats2half2_rn(x, y);
    return *(unsigned*)&h;
}
__device__ __forceinline__ uint32_t s2u(const void* p)
{
    return (uint32_t)__cvta_generic_to_shared(p);
}
__device__ __forceinline__ void ldsm4(unsigned r[4], uint32_t a)
{
    asm volatile("ldmatrix.sync.aligned.m8n8.x4.shared.b16 {%0,%1,%2,%3}, [%4];"
                 : "=r"(r[0]), "=r"(r[1]), "=r"(r[2]), "=r"(r[3]) : "r"(a));
}
__device__ __forceinline__ void ldsm4t(unsigned r[4], uint32_t a)
{
    asm volatile("ldmatrix.sync.aligned.m8n8.x4.trans.shared.b16 {%0,%1,%2,%3}, [%4];"
                 : "=r"(r[0]), "=r"(r[1]), "=r"(r[2]), "=r"(r[3]) : "r"(a));
}
__device__ __forceinline__ void cpa16(uint32_t d, const void* s)
{
    asm volatile("cp.async.ca.shared.global [%0], [%1], 16;" :: "r"(d), "l"(s));
}
__device__ __forceinline__ void cp_commit() { asm volatile("cp.async.commit_group;"); }

// ---------------------------------------------------------------------------
__global__ void f2h(const float* __restrict__ src, __half* __restrict__ dst, int n4)
{
    int i = blockIdx.x * blockDim.x + threadIdx.x;
    if (i >= n4) return;
    float4 v = ((const float4*)src)[i];
    ((__half2*)dst)[i*2]   = __floats2half2_rn(v.x, v.y);
    ((__half2*)dst)[i*2+1] = __floats2half2_rn(v.z, v.w);
}

// ---------------------------------------------------------------------------
// Tensor-core GEMM, 128x128 block, k-chunk 64, 2-stage cp.async pipeline,
// all fragments via ldmatrix.  qkv=1: fused QKV (grid.x = 24, wsel = bx>>3),
// writes fp16 scattered [B,H,S,D].  qkv=0: Wo, writes fp32 [M,N] + bias.
// ---------------------------------------------------------------------------
#define APAD 72
#define BPAD 136

__global__ __launch_bounds__(256)
void gemm_tc(const __half* __restrict__ A,
             const float* __restrict__ bq, const float* __restrict__ bk,
             const float* __restrict__ bv, float* __restrict__ Cout, int qkv)
{
    extern __shared__ __half sm[];
    __half (*As)[128][APAD] = (__half(*)[128][APAD])sm;
    __half (*Bs)[64][BPAD]  = (__half(*)[64][BPAD])(sm + 2*128*APAD);

    int wsel, n0;
    if (qkv) { wsel = blockIdx.x >> 3; n0 = (blockIdx.x & 7) * 128; }
    else     { wsel = 3;               n0 = blockIdx.x * 128; }
    const int m0 = blockIdx.y * 128;
    const __half* W = g_Wh + (size_t)wsel * EM * EM;
    const float* bias = qkv ? (wsel == 0 ? bq : (wsel == 1 ? bk : bv)) : bq;

    const int tid = threadIdx.x;
    const int wid = tid >> 5, lane = tid & 31;
    const int g = lane >> 2, tig = lane & 3;
    const int wm = (wid >> 2) * 64, wn = (wid & 3) * 32;

    auto prefetch = [&](int kt, int st) {
        int k0 = kt * 64;
#pragma unroll
        for (int i = 0; i < 4; i++) {
            int c = tid + 256 * i;
            int r = c >> 3, s = (c & 7) * 8;
            cpa16(s2u(&As[st][r][s]), A + (size_t)(m0 + r) * EM + k0 + s);
        }
#pragma unroll
        for (int i = 0; i < 4; i++) {
            int c = tid + 256 * i;
            int r = c >> 4, s = (c & 15) * 8;
            cpa16(s2u(&Bs[st][r][s]), W + (size_t)(k0 + r) * EM + n0 + s);
        }
        cp_commit();
    };

    float c[4][4][4] = {};
    prefetch(0, 0);
    const int NIT = EM / 64;
    for (int kt = 0; kt < NIT; kt++) {
        if (kt + 1 < NIT) {
            prefetch(kt + 1, (kt + 1) & 1);
            asm volatile("cp.async.wait_group 1;");
        } else {
            asm volatile("cp.async.wait_group 0;");
        }
        __syncthreads();
        const int st = kt & 1;
#pragma unroll
        for (int t = 0; t < 4; t++) {
            const int kk = t * 16;
            unsigned a[4][4];
#pragma unroll
            for (int i = 0; i < 4; i++)
                ldsm4(a[i], s2u(&As[st][wm + 16*i + (lane & 15)][kk + (lane >> 4) * 8]));
            unsigned bb[2][4];
#pragma unroll
            for (int jp = 0; jp < 2; jp++)
                ldsm4t(bb[jp], s2u(&Bs[st][kk + (lane & 15)][wn + jp*16 + (lane >> 4) * 8]));
#pragma unroll
            for (int i = 0; i < 4; i++)
#pragma unroll
                for (int j = 0; j < 4; j++)
                    mma16816(c[i][j], a[i], bb[j >> 1][(j & 1) * 2], bb[j >> 1][(j & 1) * 2 + 1]);
        }
        __syncthreads();
    }

    // Epilogue
#pragma unroll
    for (int j = 0; j < 4; j++) {
        int col = n0 + wn + j * 8 + tig * 2;
        float bi0 = bias[col], bi1 = bias[col + 1];
#pragma unroll
        for (int i = 0; i < 4; i++) {
            int r0 = m0 + wm + 16 * i + g, r1 = r0 + 8;
            float v00 = c[i][j][0] + bi0, v01 = c[i][j][1] + bi1;
            float v10 = c[i][j][2] + bi0, v11 = c[i][j][3] + bi1;
            if (!qkv) {
                *(float2*)(Cout + (size_t)r0 * EM + col) = make_float2(v00, v01);
                *(float2*)(Cout + (size_t)r1 * EM + col) = make_float2(v10, v11);
            } else {
                __half* Out = wsel == 0 ? g_Qh : (wsel == 1 ? g_Kh : g_Vh);
                int hh = col >> 6, d = col & 63;
                int bb0 = r0 >> 11, s0 = r0 & 2047;
                int bb1 = r1 >> 11, s1 = r1 & 2047;
                *(__half2*)(Out + (((size_t)(bb0*NH + hh) * SQ + s0) * HD) + d) =
                    __floats2half2_rn(v00, v01);
                *(__half2*)(Out + (((size_t)(bb1*NH + hh) * SQ + s1) * HD) + d) =
                    __floats2half2_rn(v10, v11);
            }
        }
    }
}

// ---------------------------------------------------------------------------
// L2-normalize fp16 rows of length 64 in place (fp32 math). One warp/row.
// ---------------------------------------------------------------------------
__global__ void l2norm_h(__half* __restrict__ P, int rows)
{
    int w = (blockIdx.x * blockDim.x + threadIdx.x) >> 5;
    int lane = threadIdx.x & 31;
    if (w >= rows) return;
    __half2* p = (__half2*)(P + (size_t)w * HD);
    __half2 hv = p[lane];
    float2 f = __half22float2(hv);
    float ss = f.x * f.x + f.y * f.y;
#pragma unroll
    for (int o = 16; o > 0; o >>= 1)
        ss += __shfl_xor_sync(0xffffffff, ss, o);
    float sc = 1.0f / (sqrtf(ss) + 1e-8f);
    p[lane] = __floats2half2_rn(f.x * sc, f.y * sc);
}

// ---------------------------------------------------------------------------
// Yat attention, tensor cores. Block = (b, h, 128 queries), 8 warps.
// K/V tiles (64 keys) double-buffered via cp.async; frags via ldmatrix.
// K: non-trans from [key][d]; V: .trans from [key][d]. P stays in registers.
// ---------------------------------------------------------------------------
__global__ __launch_bounds__(256)
void yat_attn2(const __half* __restrict__ Q, const __half* __restrict__ K,
               const __half* __restrict__ V, __half* __restrict__ ctx)
{
    extern __shared__ __half sm[];
    __half (*Qs)[APAD]     = (__half(*)[APAD])sm;                       // [128][72]
    __half (*Ks)[64][APAD] = (__half(*)[64][APAD])(sm + 128*APAD);      // [2][64][72]
    __half (*Vs)[64][APAD] = (__half(*)[64][APAD])(sm + 128*APAD + 2*64*APAD);

    const int q0 = blockIdx.x * 128;
    const int h  = blockIdx.y;
    const int bb = blockIdx.z;
    const size_t base = ((size_t)bb * NH + h) * SQ * HD;
    const int tid = threadIdx.x;
    const int wid = tid >> 5, lane = tid & 31;
    const int g = lane >> 2, tig = lane & 3;
    const int qr = wid * 16;

    // Q tile: 128 rows x 64, 1024 16B-chunks, 4 per thread (plain loads)
#pragma unroll
    for (int i = 0; i < 4; i++) {
        int c = tid + 256 * i;
        int r = c >> 3, s = (c & 7) * 8;
        *(uint4*)&Qs[r][s] = *(const uint4*)(Q + base + (size_t)(q0 + r) * HD + s);
    }

    auto prefetchKV = [&](int kt, int st) {
        int k0 = kt * 64;
#pragma unroll
        for (int i = 0; i < 2; i++) {
            int c = tid + 256 * i;
            int r = c >> 3, s = (c & 7) * 8;
            cpa16(s2u(&Ks[st][r][s]), K + base + (size_t)(k0 + r) * HD + s);
            cpa16(s2u(&Vs[st][r][s]), V + base + (size_t)(k0 + r) * HD + s);
        }
        cp_commit();
    };

    prefetchKV(0, 0);
    __syncthreads();   // Qs visible

    unsigned qa[4][4];
#pragma unroll
    for (int t = 0; t < 4; t++)
        ldsm4(qa[t], s2u(&Qs[qr + (lane & 15)][t*16 + (lane >> 4) * 8]));

    float o[8][4] = {};
    float den0 = 0.0f, den1 = 0.0f;

    const int NT = SQ / 64;
    for (int kt = 0; kt < NT; kt++) {
        if (kt + 1 < NT) {
            prefetchKV(kt + 1, (kt + 1) & 1);
            asm volatile("cp.async.wait_group 1;");
        } else {
            asm volatile("cp.async.wait_group 0;");
        }
        __syncthreads();
        const int st = kt & 1;

        // QK^T: 16 q x 64 keys x 64 d
        float sc[8][4] = {};
#pragma unroll
        for (int t = 0; t < 4; t++) {
            const int kk = t * 16;
#pragma unroll
            for (int jp = 0; jp < 4; jp++) {
                unsigned kb[4];
                ldsm4(kb, s2u(&Ks[st][jp*16 + ((lane >> 4) << 3) + (lane & 7)]
                                       [kk + ((lane >> 3) & 1) * 8]));
                mma16816(sc[jp*2],     qa[t], kb[0], kb[1]);
                mma16816(sc[jp*2 + 1], qa[t], kb[2], kb[3]);
            }
        }

        // Yat transform + denominator partials
#pragma unroll
        for (int j = 0; j < 8; j++) {
#pragma unroll
            for (int r = 0; r < 4; r++) {
                float dot = sc[j][r];
                float t1 = 1.0f + dot;
                sc[j][r] = t1 * t1 / (0.1f + (1.0f - dot));
            }
            den0 += sc[j][0] + sc[j][1];
            den1 += sc[j][2] + sc[j][3];
        }

        // P fp16 A-fragments from C-fragment registers
        unsigned ph[4][4];
#pragma unroll
        for (int t = 0; t < 4; t++) {
            ph[t][0] = packh2(sc[2*t][0],   sc[2*t][1]);
            ph[t][1] = packh2(sc[2*t][2],   sc[2*t][3]);
            ph[t][2] = packh2(sc[2*t+1][0], sc[2*t+1][1]);
            ph[t][3] = packh2(sc[2*t+1][2], sc[2*t+1][3]);
        }

        // P @ V: 16 q x 64 d x 64 keys
#pragma unroll
        for (int t = 0; t < 4; t++) {
            const int kk = t * 16;
#pragma unroll
            for (int jp = 0; jp < 4; jp++) {
                unsigned vb[4];
                ldsm4t(vb, s2u(&Vs[st][kk + ((lane >> 3) & 1) * 8 + (lane & 7)]
                                        [jp*16 + (lane >> 4) * 8]));
                mma16816(o[jp*2],     ph[t], vb[0], vb[1]);
                mma16816(o[jp*2 + 1], ph[t], vb[2], vb[3]);
            }
        }
        __syncthreads();
    }

    // Reduce denominators across tig lanes (rows are in lanes g, g+8 halves)
    den0 += __shfl_xor_sync(0xffffffff, den0, 1);
    den0 += __shfl_xor_sync(0xffffffff, den0, 2);
    den1 += __shfl_xor_sync(0xffffffff, den1, 1);
    den1 += __shfl_xor_sync(0xffffffff, den1, 2);
    float inv0 = 1.0f / (den0 + 1e-6f);
    float inv1 = 1.0f / (den1 + 1e-6f);

    const size_t obase = (size_t)bb * SQ * EM + (size_t)h * HD;
    int r0 = q0 + qr + g, r1 = r0 + 8;
#pragma unroll
    for (int j = 0; j < 8; j++) {
        int col = j * 8 + tig * 2;
        *(__half2*)(ctx + obase + (size_t)r0 * EM + col) =
            __floats2half2_rn(o[j][0] * inv0, o[j][1] * inv0);
        *(__half2*)(ctx + obase + (size_t)r1 * EM + col) =
            __floats2half2_rn(o[j][2] * inv1, o[j][3] * inv1);
    }
}

// ---------------------------------------------------------------------------
extern "C" void kernel_launch(void* const* d_in, const int* in_sizes, int n_in,
                              void* d_out, int out_size)
{
    const float* x  = (const float*)d_in[0];
    const float* Wq = (const float*)d_in[1];
    const float* bq = (const float*)d_in[2];
    const float* Wk = (const float*)d_in[3];
    const float* bk = (const float*)d_in[4];
    const float* Wv = (const float*)d_in[5];
    const float* bv = (const float*)d_in[6];
    const float* Wo = (const float*)d_in[7];
    const float* bo = (const float*)d_in[8];
    float* out = (float*)d_out;

    __half *dXh, *dWh, *dQh, *dKh, *dVh, *dCh;
    cudaGetSymbolAddress((void**)&dXh, g_Xh);
    cudaGetSymbolAddress((void**)&dWh, g_Wh);
    cudaGetSymbolAddress((void**)&dQh, g_Qh);
    cudaGetSymbolAddress((void**)&dKh, g_Kh);
    cudaGetSymbolAddress((void**)&dVh, g_Vh);
    cudaGetSymbolAddress((void**)&dCh, g_Ch);

    const int M = NB * SQ;

    // fp32 -> fp16 staging
    int n4x = (M * EM) / 4;
    f2h<<<(n4x + 255) / 256, 256>>>(x, dXh, n4x);
    int n4w = (EM * EM) / 4;
    f2h<<<(n4w + 255) / 256, 256>>>(Wq, dWh + 0 * (size_t)EM * EM, n4w);
    f2h<<<(n4w + 255) / 256, 256>>>(Wk, dWh + 1 * (size_t)EM * EM, n4w);
    f2h<<<(n4w + 255) / 256, 256>>>(Wv, dWh + 2 * (size_t)EM * EM, n4w);
    f2h<<<(n4w + 255) / 256, 256>>>(Wo, dWh + 3 * (size_t)EM * EM, n4w);

    const int gemm_smem = 2*128*APAD*2 + 2*64*BPAD*2;   // 71,680 B
    cudaFuncSetAttribute(gemm_tc, cudaFuncAttributeMaxDynamicSharedMemorySize, gemm_smem);

    // Fused QKV
    gemm_tc<<<dim3(24, M / 128), 256, gemm_smem>>>(dXh, bq, bk, bv, nullptr, 1);

    int rows = NB * NH * SQ;
    int nthreads = rows * 32;
    l2norm_h<<<(nthreads + 255) / 256, 256>>>(dQh, rows);
    l2norm_h<<<(nthreads + 255) / 256, 256>>>(dKh, rows);

    const int attn_smem = (128*APAD + 4*64*APAD) * 2;   // 55,296 B
    cudaFuncSetAttribute(yat_attn2, cudaFuncAttributeMaxDynamicSharedMemorySize, attn_smem);
    yat_attn2<<<dim3(SQ / 128, NH, NB), 256, attn_smem>>>(dQh, dKh, dVh, dCh);

    // Output projection
    gemm_tc<<<dim3(8, M / 128), 256, gemm_smem>>>(dCh, bo, nullptr, nullptr, out, 0);
}

// round 7
// speedup vs baseline: 5.9354x; 1.0066x over previous
#include <cuda_runtime.h>
#include <cuda_fp16.h>
#include <cstdint>
#include <math.h>

#define NB 2
#define NH 16
#define HD 64
#define SQ 2048
#define EM 1024

// Scratch (device globals; runtime allocation is forbidden)
__device__ __align__(256) __half g_Xh[(size_t)NB*SQ*EM];
__device__ __align__(256) __half g_Wh[(size_t)4*EM*EM];   // Wq,Wk,Wv,Wo fp16
__device__ __align__(256) __half g_Qh[(size_t)NB*NH*SQ*HD];
__device__ __align__(256) __half g_Kh[(size_t)NB*NH*SQ*HD];
__device__ __align__(256) __half g_Vh[(size_t)NB*NH*SQ*HD];
__device__ __align__(256) __half g_Ch[(size_t)NB*SQ*EM];

// ---------------------------------------------------------------------------
__device__ __forceinline__ void mma16816(float c[4], const unsigned a[4],
                                         unsigned b0, unsigned b1)
{
    asm volatile(
        "mma.sync.aligned.m16n8k16.row.col.f32.f16.f16.f32 "
        "{%0,%1,%2,%3}, {%4,%5,%6,%7}, {%8,%9}, {%0,%1,%2,%3};\n"
        : "+f"(c[0]), "+f"(c[1]), "+f"(c[2]), "+f"(c[3])
        : "r"(a[0]), "r"(a[1]), "r"(a[2]), "r"(a[3]), "r"(b0), "r"(b1));
}
__device__ __forceinline__ unsigned packh2(float x, float y)
{
    __half2 h = __floats2half2_rn(x, y);
    return *(unsigned*)&h;
}
__device__ __forceinline__ uint32_t s2u(const void* p)
{
    return (uint32_t)__cvta_generic_to_shared(p);
}
__device__ __forceinline__ void ldsm4(unsigned r[4], uint32_t a)
{
    asm volatile("ldmatrix.sync.aligned.m8n8.x4.shared.b16 {%0,%1,%2,%3}, [%4];"
                 : "=r"(r[0]), "=r"(r[1]), "=r"(r[2]), "=r"(r[3]) : "r"(a));
}
__device__ __forceinline__ void ldsm4t(unsigned r[4], uint32_t a)
{
    asm volatile("ldmatrix.sync.aligned.m8n8.x4.trans.shared.b16 {%0,%1,%2,%3}, [%4];"
                 : "=r"(r[0]), "=r"(r[1]), "=r"(r[2]), "=r"(r[3]) : "r"(a));
}
__device__ __forceinline__ void cpa16(uint32_t d, const void* s)
{
    asm volatile("cp.async.ca.shared.global [%0], [%1], 16;" :: "r"(d), "l"(s));
}
__device__ __forceinline__ void cp_commit() { asm volatile("cp.async.commit_group;"); }
__device__ __forceinline__ void cp_wait_tail(bool more)
{
    if (more) asm volatile("cp.async.wait_group 1;");
    else      asm volatile("cp.async.wait_group 0;");
}

// ---------------------------------------------------------------------------
__global__ void f2h(const float* __restrict__ src, __half* __restrict__ dst, int n4)
{
    int i = blockIdx.x * blockDim.x + threadIdx.x;
    if (i >= n4) return;
    float4 v = ((const float4*)src)[i];
    ((__half2*)dst)[i*2]   = __floats2half2_rn(v.x, v.y);
    ((__half2*)dst)[i*2+1] = __floats2half2_rn(v.z, v.w);
}

// ---------------------------------------------------------------------------
// Tensor-core GEMM, 128x128 block, k-chunk 64, 3-stage cp.async pipeline with
// ONE __syncthreads per iteration (wait -> sync -> prefetch -> compute).
// qkv=1: fused QKV (grid.x = 24, wsel = bx>>3), L2-norm fused for Q/K,
//        writes fp16 scattered [B,H,S,D].  qkv=0: Wo, fp32 [M,N] + bias.
// ---------------------------------------------------------------------------
#define APAD 72
#define BPAD 136

__global__ __launch_bounds__(256)
void gemm_tc(const __half* __restrict__ A,
             const float* __restrict__ bq, const float* __restrict__ bk,
             const float* __restrict__ bv, float* __restrict__ Cout, int qkv)
{
    extern __shared__ __half sm[];
    __half (*As)[128][APAD] = (__half(*)[128][APAD])sm;
    __half (*Bs)[64][BPAD]  = (__half(*)[64][BPAD])(sm + 3*128*APAD);

    int wsel, n0;
    if (qkv) { wsel = blockIdx.x >> 3; n0 = (blockIdx.x & 7) * 128; }
    else     { wsel = 3;               n0 = blockIdx.x * 128; }
    const int m0 = blockIdx.y * 128;
    const __half* W = g_Wh + (size_t)wsel * EM * EM;
    const float* bias = qkv ? (wsel == 0 ? bq : (wsel == 1 ? bk : bv)) : bq;

    const int tid = threadIdx.x;
    const int wid = tid >> 5, lane = tid & 31;
    const int g = lane >> 2, tig = lane & 3;
    const int wm = (wid >> 2) * 64, wn = (wid & 3) * 32;

    auto prefetch = [&](int kt, int st) {
        int k0 = kt * 64;
#pragma unroll
        for (int i = 0; i < 4; i++) {
            int c = tid + 256 * i;
            int r = c >> 3, s = (c & 7) * 8;
            cpa16(s2u(&As[st][r][s]), A + (size_t)(m0 + r) * EM + k0 + s);
        }
#pragma unroll
        for (int i = 0; i < 4; i++) {
            int c = tid + 256 * i;
            int r = c >> 4, s = (c & 15) * 8;
            cpa16(s2u(&Bs[st][r][s]), W + (size_t)(k0 + r) * EM + n0 + s);
        }
        cp_commit();
    };

    float c[4][4][4] = {};
    prefetch(0, 0);
    prefetch(1, 1);
    const int NIT = EM / 64;
    for (int kt = 0; kt < NIT; kt++) {
        cp_wait_tail(kt + 1 < NIT);
        __syncthreads();
        if (kt + 2 < NIT) prefetch(kt + 2, (kt + 2) % 3);
        const int st = kt % 3;
#pragma unroll
        for (int t = 0; t < 4; t++) {
            const int kk = t * 16;
            unsigned a[4][4];
#pragma unroll
            for (int i = 0; i < 4; i++)
                ldsm4(a[i], s2u(&As[st][wm + 16*i + (lane & 15)][kk + (lane >> 4) * 8]));
            unsigned bb[2][4];
#pragma unroll
            for (int jp = 0; jp < 2; jp++)
                ldsm4t(bb[jp], s2u(&Bs[st][kk + (lane & 15)][wn + jp*16 + (lane >> 4) * 8]));
#pragma unroll
            for (int i = 0; i < 4; i++)
#pragma unroll
                for (int j = 0; j < 4; j++)
                    mma16816(c[i][j], a[i], bb[j >> 1][(j & 1) * 2], bb[j >> 1][(j & 1) * 2 + 1]);
        }
    }

    // ---- Epilogue: add bias in place ----
#pragma unroll
    for (int j = 0; j < 4; j++) {
        int col = n0 + wn + j * 8 + tig * 2;
        float bi0 = bias[col], bi1 = bias[col + 1];
#pragma unroll
        for (int i = 0; i < 4; i++) {
            c[i][j][0] += bi0; c[i][j][1] += bi1;
            c[i][j][2] += bi0; c[i][j][3] += bi1;
        }
    }

    // ---- Fused L2 norm for Q/K (per row within each 64-col head) ----
    if (qkv && wsel < 2) {
        float sq0[4], sq1[4];
#pragma unroll
        for (int i = 0; i < 4; i++) {
            sq0[i] = 0.0f; sq1[i] = 0.0f;
#pragma unroll
            for (int j = 0; j < 4; j++) {
                sq0[i] += c[i][j][0]*c[i][j][0] + c[i][j][1]*c[i][j][1];
                sq1[i] += c[i][j][2]*c[i][j][2] + c[i][j][3]*c[i][j][3];
            }
        }
#pragma unroll
        for (int i = 0; i < 4; i++) {
            sq0[i] += __shfl_xor_sync(0xffffffffu, sq0[i], 1);
            sq0[i] += __shfl_xor_sync(0xffffffffu, sq0[i], 2);
            sq1[i] += __shfl_xor_sync(0xffffffffu, sq1[i], 1);
            sq1[i] += __shfl_xor_sync(0xffffffffu, sq1[i], 2);
        }
        float* ss = (float*)sm;   // [8 warps][64 rows] = 2 KB, reuse tile smem
        __syncthreads();          // everyone out of the mainloop smem
        if (tig == 0) {
#pragma unroll
            for (int i = 0; i < 4; i++) {
                ss[wid*64 + 16*i + g]     = sq0[i];
                ss[wid*64 + 16*i + g + 8] = sq1[i];
            }
        }
        __syncthreads();
        const int pw = wid ^ 1;   // partner warp covering the other 32 cols of head
#pragma unroll
        for (int i = 0; i < 4; i++) {
            float t0 = ss[wid*64 + 16*i + g]     + ss[pw*64 + 16*i + g];
            float t1 = ss[wid*64 + 16*i + g + 8] + ss[pw*64 + 16*i + g + 8];
            float s0 = 1.0f / (sqrtf(t0) + 1e-8f);
            float s1 = 1.0f / (sqrtf(t1) + 1e-8f);
#pragma unroll
            for (int j = 0; j < 4; j++) {
                c[i][j][0] *= s0; c[i][j][1] *= s0;
                c[i][j][2] *= s1; c[i][j][3] *= s1;
            }
        }
    }

    // ---- Write out ----
#pragma unroll
    for (int j = 0; j < 4; j++) {
        int col = n0 + wn + j * 8 + tig * 2;
#pragma unroll
        for (int i = 0; i < 4; i++) {
            int r0 = m0 + wm + 16 * i + g, r1 = r0 + 8;
            if (!qkv) {
                *(float2*)(Cout + (size_t)r0 * EM + col) = make_float2(c[i][j][0], c[i][j][1]);
                *(float2*)(Cout + (size_t)r1 * EM + col) = make_float2(c[i][j][2], c[i][j][3]);
            } else {
                __half* Out = wsel == 0 ? g_Qh : (wsel == 1 ? g_Kh : g_Vh);
                int hh = col >> 6, d = col & 63;
                int bb0 = r0 >> 11, s0 = r0 & 2047;
                int bb1 = r1 >> 11, s1 = r1 & 2047;
                *(__half2*)(Out + (((size_t)(bb0*NH + hh) * SQ + s0) * HD) + d) =
                    __floats2half2_rn(c[i][j][0], c[i][j][1]);
                *(__half2*)(Out + (((size_t)(bb1*NH + hh) * SQ + s1) * HD) + d) =
                    __floats2half2_rn(c[i][j][2], c[i][j][3]);
            }
        }
    }
}

// ---------------------------------------------------------------------------
// Yat attention, tensor cores. Block = (b, h, 128 queries), 8 warps.
// K/V tiles (64 keys) 3-stage cp.async pipeline, ONE sync per tile.
// K: non-trans from [key][d]; V: .trans from [key][d]. P stays in registers.
// ---------------------------------------------------------------------------
__global__ __launch_bounds__(256)
void yat_attn2(const __half* __restrict__ Q, const __half* __restrict__ K,
               const __half* __restrict__ V, __half* __restrict__ ctx)
{
    extern __shared__ __half sm[];
    __half (*Qs)[APAD]     = (__half(*)[APAD])sm;                       // [128][72]
    __half (*Ks)[64][APAD] = (__half(*)[64][APAD])(sm + 128*APAD);      // [3][64][72]
    __half (*Vs)[64][APAD] = (__half(*)[64][APAD])(sm + 128*APAD + 3*64*APAD);

    const int q0 = blockIdx.x * 128;
    const int h  = blockIdx.y;
    const int bb = blockIdx.z;
    const size_t base = ((size_t)bb * NH + h) * SQ * HD;
    const int tid = threadIdx.x;
    const int wid = tid >> 5, lane = tid & 31;
    const int g = lane >> 2, tig = lane & 3;
    const int qr = wid * 16;

    auto prefetchKV = [&](int kt, int st) {
        int k0 = kt * 64;
#pragma unroll
        for (int i = 0; i < 2; i++) {
            int c = tid + 256 * i;
            int r = c >> 3, s = (c & 7) * 8;
            cpa16(s2u(&Ks[st][r][s]), K + base + (size_t)(k0 + r) * HD + s);
            cpa16(s2u(&Vs[st][r][s]), V + base + (size_t)(k0 + r) * HD + s);
        }
        cp_commit();
    };

    prefetchKV(0, 0);
    prefetchKV(1, 1);

    // Q tile: 128 rows x 64 (plain loads overlap the cp.async prologue)
#pragma unroll
    for (int i = 0; i < 4; i++) {
        int c = tid + 256 * i;
        int r = c >> 3, s = (c & 7) * 8;
        *(uint4*)&Qs[r][s] = *(const uint4*)(Q + base + (size_t)(q0 + r) * HD + s);
    }
    __syncthreads();   // Qs visible

    unsigned qa[4][4];
#pragma unroll
    for (int t = 0; t < 4; t++)
        ldsm4(qa[t], s2u(&Qs[qr + (lane & 15)][t*16 + (lane >> 4) * 8]));

    float o[8][4] = {};
    float den0 = 0.0f, den1 = 0.0f;

    const int NT = SQ / 64;
    for (int kt = 0; kt < NT; kt++) {
        cp_wait_tail(kt + 1 < NT);
        __syncthreads();
        if (kt + 2 < NT) prefetchKV(kt + 2, (kt + 2) % 3);
        const int st = kt % 3;

        // QK^T: 16 q x 64 keys x 64 d
        float sc[8][4] = {};
#pragma unroll
        for (int t = 0; t < 4; t++) {
            const int kk = t * 16;
#pragma unroll
            for (int jp = 0; jp < 4; jp++) {
                unsigned kb[4];
                ldsm4(kb, s2u(&Ks[st][jp*16 + ((lane >> 4) << 3) + (lane & 7)]
                                       [kk + ((lane >> 3) & 1) * 8]));
                mma16816(sc[jp*2],     qa[t], kb[0], kb[1]);
                mma16816(sc[jp*2 + 1], qa[t], kb[2], kb[3]);
            }
        }

        // Yat transform + denominator partials
#pragma unroll
        for (int j = 0; j < 8; j++) {
#pragma unroll
            for (int r = 0; r < 4; r++) {
                float dot = sc[j][r];
                float t1 = 1.0f + dot;
                sc[j][r] = t1 * t1 / (0.1f + (1.0f - dot));
            }
            den0 += sc[j][0] + sc[j][1];
            den1 += sc[j][2] + sc[j][3];
        }

        // P fp16 A-fragments from C-fragment registers
        unsigned ph[4][4];
#pragma unroll
        for (int t = 0; t < 4; t++) {
            ph[t][0] = packh2(sc[2*t][0],   sc[2*t][1]);
            ph[t][1] = packh2(sc[2*t][2],   sc[2*t][3]);
            ph[t][2] = packh2(sc[2*t+1][0], sc[2*t+1][1]);
            ph[t][3] = packh2(sc[2*t+1][2], sc[2*t+1][3]);
        }

        // P @ V: 16 q x 64 d x 64 keys
#pragma unroll
        for (int t = 0; t < 4; t++) {
            const int kk = t * 16;
#pragma unroll
            for (int jp = 0; jp < 4; jp++) {
                unsigned vb[4];
                ldsm4t(vb, s2u(&Vs[st][kk + ((lane >> 3) & 1) * 8 + (lane & 7)]
                                        [jp*16 + (lane >> 4) * 8]));
                mma16816(o[jp*2],     ph[t], vb[0], vb[1]);
                mma16816(o[jp*2 + 1], ph[t], vb[2], vb[3]);
            }
        }
    }

    // Reduce denominators across tig lanes
    den0 += __shfl_xor_sync(0xffffffff, den0, 1);
    den0 += __shfl_xor_sync(0xffffffff, den0, 2);
    den1 += __shfl_xor_sync(0xffffffff, den1, 1);
    den1 += __shfl_xor_sync(0xffffffff, den1, 2);
    float inv0 = 1.0f / (den0 + 1e-6f);
    float inv1 = 1.0f / (den1 + 1e-6f);

    const size_t obase = (size_t)bb * SQ * EM + (size_t)h * HD;
    int r0 = q0 + qr + g, r1 = r0 + 8;
#pragma unroll
    for (int j = 0; j < 8; j++) {
        int col = j * 8 + tig * 2;
        *(__half2*)(ctx + obase + (size_t)r0 * EM + col) =
            __floats2half2_rn(o[j][0] * inv0, o[j][1] * inv0);
        *(__half2*)(ctx + obase + (size_t)r1 * EM + col) =
            __floats2half2_rn(o[j][2] * inv1, o[j][3] * inv1);
    }
}

// ---------------------------------------------------------------------------
extern "C" void kernel_launch(void* const* d_in, const int* in_sizes, int n_in,
                              void* d_out, int out_size)
{
    const float* x  = (const float*)d_in[0];
    const float* Wq = (const float*)d_in[1];
    const float* bq = (const float*)d_in[2];
    const float* Wk = (const float*)d_in[3];
    const float* bk = (const float*)d_in[4];
    const float* Wv = (const float*)d_in[5];
    const float* bv = (const float*)d_in[6];
    const float* Wo = (const float*)d_in[7];
    const float* bo = (const float*)d_in[8];
    float* out = (float*)d_out;

    __half *dXh, *dWh, *dCh;
    cudaGetSymbolAddress((void**)&dXh, g_Xh);
    cudaGetSymbolAddress((void**)&dWh, g_Wh);
    cudaGetSymbolAddress((void**)&dCh, g_Ch);
    __half *dQh, *dKh, *dVh;
    cudaGetSymbolAddress((void**)&dQh, g_Qh);
    cudaGetSymbolAddress((void**)&dKh, g_Kh);
    cudaGetSymbolAddress((void**)&dVh, g_Vh);

    const int M = NB * SQ;

    // fp32 -> fp16 staging
    int n4x = (M * EM) / 4;
    f2h<<<(n4x + 255) / 256, 256>>>(x, dXh, n4x);
    int n4w = (EM * EM) / 4;
    f2h<<<(n4w + 255) / 256, 256>>>(Wq, dWh + 0 * (size_t)EM * EM, n4w);
    f2h<<<(n4w + 255) / 256, 256>>>(Wk, dWh + 1 * (size_t)EM * EM, n4w);
    f2h<<<(n4w + 255) / 256, 256>>>(Wv, dWh + 2 * (size_t)EM * EM, n4w);
    f2h<<<(n4w + 255) / 256, 256>>>(Wo, dWh + 3 * (size_t)EM * EM, n4w);

    const int gemm_smem = 3*128*APAD*2 + 3*64*BPAD*2;   // 107,520 B
    cudaFuncSetAttribute(gemm_tc, cudaFuncAttributeMaxDynamicSharedMemorySize, gemm_smem);

    // Fused QKV (+ fused L2 norm on Q/K)
    gemm_tc<<<dim3(24, M / 128), 256, gemm_smem>>>(dXh, bq, bk, bv, nullptr, 1);

    const int attn_smem = (128*APAD + 6*64*APAD) * 2;   // 73,728 B
    cudaFuncSetAttribute(yat_attn2, cudaFuncAttributeMaxDynamicSharedMemorySize, attn_smem);
    yat_attn2<<<dim3(SQ / 128, NH, NB), 256, attn_smem>>>(dQh, dKh, dVh, dCh);

    // Output projection
    gemm_tc<<<dim3(8, M / 128), 256, gemm_smem>>>(dCh, bo, nullptr, nullptr, out, 0);
}

// round 8
// speedup vs baseline: 7.1533x; 1.2052x over previous
#include <cuda_runtime.h>
#include <cuda_fp16.h>
#include <cstdint>
#include <math.h>

#define NB 2
#define NH 16
#define HD 64
#define SQ 2048
#define EM 1024

// Scratch (device globals; runtime allocation is forbidden)
__device__ __align__(256) __half g_Xh[(size_t)NB*SQ*EM];
__device__ __align__(256) __half g_Wh[(size_t)4*EM*EM];   // Wq,Wk,Wv,Wo fp16
__device__ __align__(256) __half g_Qh[(size_t)NB*NH*SQ*HD];
__device__ __align__(256) __half g_Kh[(size_t)NB*NH*SQ*HD];
__device__ __align__(256) __half g_Vh[(size_t)NB*NH*SQ*HD];
__device__ __align__(256) __half g_Ch[(size_t)NB*SQ*EM];

// ---------------------------------------------------------------------------
__device__ __forceinline__ void mma16816(float c[4], const unsigned a[4],
                                         unsigned b0, unsigned b1)
{
    asm volatile(
        "mma.sync.aligned.m16n8k16.row.col.f32.f16.f16.f32 "
        "{%0,%1,%2,%3}, {%4,%5,%6,%7}, {%8,%9}, {%0,%1,%2,%3};\n"
        : "+f"(c[0]), "+f"(c[1]), "+f"(c[2]), "+f"(c[3])
        : "r"(a[0]), "r"(a[1]), "r"(a[2]), "r"(a[3]), "r"(b0), "r"(b1));
}
__device__ __forceinline__ unsigned packh2(float x, float y)
{
    __half2 h = __floats2half2_rn(x, y);
    return *(unsigned*)&h;
}
__device__ __forceinline__ uint32_t s2u(const void* p)
{
    return (uint32_t)__cvta_generic_to_shared(p);
}
__device__ __forceinline__ void ldsm4(unsigned r[4], uint32_t a)
{
    asm volatile("ldmatrix.sync.aligned.m8n8.x4.shared.b16 {%0,%1,%2,%3}, [%4];"
                 : "=r"(r[0]), "=r"(r[1]), "=r"(r[2]), "=r"(r[3]) : "r"(a));
}
__device__ __forceinline__ void ldsm4t(unsigned r[4], uint32_t a)
{
    asm volatile("ldmatrix.sync.aligned.m8n8.x4.trans.shared.b16 {%0,%1,%2,%3}, [%4];"
                 : "=r"(r[0]), "=r"(r[1]), "=r"(r[2]), "=r"(r[3]) : "r"(a));
}
__device__ __forceinline__ void cpa16(uint32_t d, const void* s)
{
    asm volatile("cp.async.ca.shared.global [%0], [%1], 16;" :: "r"(d), "l"(s));
}
__device__ __forceinline__ void cp_commit() { asm volatile("cp.async.commit_group;"); }
__device__ __forceinline__ void cp_wait_tail(bool more)
{
    if (more) asm volatile("cp.async.wait_group 1;");
    else      asm volatile("cp.async.wait_group 0;");
}

// ---------------------------------------------------------------------------
// Fused fp32->fp16: x (2M floats) + 4 weights (1M floats each), grid-stride.
// ---------------------------------------------------------------------------
#define X_F4   ((NB*SQ*EM)/4)       // 524288 float4s
#define W_F4   ((EM*EM)/4)          // 262144 float4s per weight
#define TOT_F4 (X_F4 + 4*W_F4)      // 1572864

__global__ void f2h_all(const float* __restrict__ x,
                        const float* __restrict__ w0, const float* __restrict__ w1,
                        const float* __restrict__ w2, const float* __restrict__ w3)
{
    __half* dstX = g_Xh;
    __half* dstW = g_Wh;
    for (int i = blockIdx.x * blockDim.x + threadIdx.x; i < TOT_F4;
         i += gridDim.x * blockDim.x) {
        const float* src; __half* dst; int off;
        if (i < X_F4) { src = x; dst = dstX; off = i; }
        else {
            int j = i - X_F4;
            int w = j / W_F4;  off = j - w * W_F4;
            src = (w == 0) ? w0 : (w == 1) ? w1 : (w == 2) ? w2 : w3;
            dst = dstW + (size_t)w * (EM * EM);
        }
        float4 v = ((const float4*)src)[off];
        ((__half2*)dst)[off*2]   = __floats2half2_rn(v.x, v.y);
        ((__half2*)dst)[off*2+1] = __floats2half2_rn(v.z, v.w);
    }
}

// ---------------------------------------------------------------------------
// Tensor-core GEMM, 128x128 block, k-chunk 64, 3-stage cp.async pipeline with
// ONE __syncthreads per iteration (wait -> sync -> prefetch -> compute).
// qkv=1: fused QKV (grid.x = 24, wsel = bx>>3), L2-norm fused for Q/K,
//        writes fp16 scattered [B,H,S,D].  qkv=0: Wo, fp32 [M,N] + bias.
// ---------------------------------------------------------------------------
#define APAD 72
#define BPAD 136

__global__ __launch_bounds__(256)
void gemm_tc(const __half* __restrict__ A,
             const float* __restrict__ bq, const float* __restrict__ bk,
             const float* __restrict__ bv, float* __restrict__ Cout, int qkv)
{
    extern __shared__ __half sm[];
    __half (*As)[128][APAD] = (__half(*)[128][APAD])sm;
    __half (*Bs)[64][BPAD]  = (__half(*)[64][BPAD])(sm + 3*128*APAD);

    int wsel, n0;
    if (qkv) { wsel = blockIdx.x >> 3; n0 = (blockIdx.x & 7) * 128; }
    else     { wsel = 3;               n0 = blockIdx.x * 128; }
    const int m0 = blockIdx.y * 128;
    const __half* W = g_Wh + (size_t)wsel * EM * EM;
    const float* bias = qkv ? (wsel == 0 ? bq : (wsel == 1 ? bk : bv)) : bq;

    const int tid = threadIdx.x;
    const int wid = tid >> 5, lane = tid & 31;
    const int g = lane >> 2, tig = lane & 3;
    const int wm = (wid >> 2) * 64, wn = (wid & 3) * 32;

    auto prefetch = [&](int kt, int st) {
        int k0 = kt * 64;
#pragma unroll
        for (int i = 0; i < 4; i++) {
            int c = tid + 256 * i;
            int r = c >> 3, s = (c & 7) * 8;
            cpa16(s2u(&As[st][r][s]), A + (size_t)(m0 + r) * EM + k0 + s);
        }
#pragma unroll
        for (int i = 0; i < 4; i++) {
            int c = tid + 256 * i;
            int r = c >> 4, s = (c & 15) * 8;
            cpa16(s2u(&Bs[st][r][s]), W + (size_t)(k0 + r) * EM + n0 + s);
        }
        cp_commit();
    };

    float c[4][4][4] = {};
    prefetch(0, 0);
    prefetch(1, 1);
    const int NIT = EM / 64;
    for (int kt = 0; kt < NIT; kt++) {
        cp_wait_tail(kt + 1 < NIT);
        __syncthreads();
        if (kt + 2 < NIT) prefetch(kt + 2, (kt + 2) % 3);
        const int st = kt % 3;
#pragma unroll
        for (int t = 0; t < 4; t++) {
            const int kk = t * 16;
            unsigned a[4][4];
#pragma unroll
            for (int i = 0; i < 4; i++)
                ldsm4(a[i], s2u(&As[st][wm + 16*i + (lane & 15)][kk + (lane >> 4) * 8]));
            unsigned bb[2][4];
#pragma unroll
            for (int jp = 0; jp < 2; jp++)
                ldsm4t(bb[jp], s2u(&Bs[st][kk + (lane & 15)][wn + jp*16 + (lane >> 4) * 8]));
#pragma unroll
            for (int i = 0; i < 4; i++)
#pragma unroll
                for (int j = 0; j < 4; j++)
                    mma16816(c[i][j], a[i], bb[j >> 1][(j & 1) * 2], bb[j >> 1][(j & 1) * 2 + 1]);
        }
    }

    // ---- Epilogue: add bias in place ----
#pragma unroll
    for (int j = 0; j < 4; j++) {
        int col = n0 + wn + j * 8 + tig * 2;
        float bi0 = bias[col], bi1 = bias[col + 1];
#pragma unroll
        for (int i = 0; i < 4; i++) {
            c[i][j][0] += bi0; c[i][j][1] += bi1;
            c[i][j][2] += bi0; c[i][j][3] += bi1;
        }
    }

    // ---- Fused L2 norm for Q/K (per row within each 64-col head) ----
    if (qkv && wsel < 2) {
        float sq0[4], sq1[4];
#pragma unroll
        for (int i = 0; i < 4; i++) {
            sq0[i] = 0.0f; sq1[i] = 0.0f;
#pragma unroll
            for (int j = 0; j < 4; j++) {
                sq0[i] += c[i][j][0]*c[i][j][0] + c[i][j][1]*c[i][j][1];
                sq1[i] += c[i][j][2]*c[i][j][2] + c[i][j][3]*c[i][j][3];
            }
        }
#pragma unroll
        for (int i = 0; i < 4; i++) {
            sq0[i] += __shfl_xor_sync(0xffffffffu, sq0[i], 1);
            sq0[i] += __shfl_xor_sync(0xffffffffu, sq0[i], 2);
            sq1[i] += __shfl_xor_sync(0xffffffffu, sq1[i], 1);
            sq1[i] += __shfl_xor_sync(0xffffffffu, sq1[i], 2);
        }
        float* ss = (float*)sm;   // [8 warps][64 rows] = 2 KB, reuse tile smem
        __syncthreads();          // everyone out of the mainloop smem
        if (tig == 0) {
#pragma unroll
            for (int i = 0; i < 4; i++) {
                ss[wid*64 + 16*i + g]     = sq0[i];
                ss[wid*64 + 16*i + g + 8] = sq1[i];
            }
        }
        __syncthreads();
        const int pw = wid ^ 1;   // partner warp covering the other 32 cols of head
#pragma unroll
        for (int i = 0; i < 4; i++) {
            float t0 = ss[wid*64 + 16*i + g]     + ss[pw*64 + 16*i + g];
            float t1 = ss[wid*64 + 16*i + g + 8] + ss[pw*64 + 16*i + g + 8];
            float s0 = 1.0f / (sqrtf(t0) + 1e-8f);
            float s1 = 1.0f / (sqrtf(t1) + 1e-8f);
#pragma unroll
            for (int j = 0; j < 4; j++) {
                c[i][j][0] *= s0; c[i][j][1] *= s0;
                c[i][j][2] *= s1; c[i][j][3] *= s1;
            }
        }
    }

    // ---- Write out ----
#pragma unroll
    for (int j = 0; j < 4; j++) {
        int col = n0 + wn + j * 8 + tig * 2;
#pragma unroll
        for (int i = 0; i < 4; i++) {
            int r0 = m0 + wm + 16 * i + g, r1 = r0 + 8;
            if (!qkv) {
                *(float2*)(Cout + (size_t)r0 * EM + col) = make_float2(c[i][j][0], c[i][j][1]);
                *(float2*)(Cout + (size_t)r1 * EM + col) = make_float2(c[i][j][2], c[i][j][3]);
            } else {
                __half* Out = wsel == 0 ? g_Qh : (wsel == 1 ? g_Kh : g_Vh);
                int hh = col >> 6, d = col & 63;
                int bb0 = r0 >> 11, s0 = r0 & 2047;
                int bb1 = r1 >> 11, s1 = r1 & 2047;
                *(__half2*)(Out + (((size_t)(bb0*NH + hh) * SQ + s0) * HD) + d) =
                    __floats2half2_rn(c[i][j][0], c[i][j][1]);
                *(__half2*)(Out + (((size_t)(bb1*NH + hh) * SQ + s1) * HD) + d) =
                    __floats2half2_rn(c[i][j][2], c[i][j][3]);
            }
        }
    }
}

// ---------------------------------------------------------------------------
// Yat attention, tensor cores. Block = (b, h, 128 queries), 8 warps.
// K/V tiles (64 keys) 3-stage cp.async pipeline, ONE sync per tile.
// Yat transform uses fast division (__fdividef; den in [0.1, 2.1]).
// ---------------------------------------------------------------------------
__global__ __launch_bounds__(256)
void yat_attn2(const __half* __restrict__ Q, const __half* __restrict__ K,
               const __half* __restrict__ V, __half* __restrict__ ctx)
{
    extern __shared__ __half sm[];
    __half (*Qs)[APAD]     = (__half(*)[APAD])sm;                       // [128][72]
    __half (*Ks)[64][APAD] = (__half(*)[64][APAD])(sm + 128*APAD);      // [3][64][72]
    __half (*Vs)[64][APAD] = (__half(*)[64][APAD])(sm + 128*APAD + 3*64*APAD);

    const int q0 = blockIdx.x * 128;
    const int h  = blockIdx.y;
    const int bb = blockIdx.z;
    const size_t base = ((size_t)bb * NH + h) * SQ * HD;
    const int tid = threadIdx.x;
    const int wid = tid >> 5, lane = tid & 31;
    const int g = lane >> 2, tig = lane & 3;
    const int qr = wid * 16;

    auto prefetchKV = [&](int kt, int st) {
        int k0 = kt * 64;
#pragma unroll
        for (int i = 0; i < 2; i++) {
            int c = tid + 256 * i;
            int r = c >> 3, s = (c & 7) * 8;
            cpa16(s2u(&Ks[st][r][s]), K + base + (size_t)(k0 + r) * HD + s);
            cpa16(s2u(&Vs[st][r][s]), V + base + (size_t)(k0 + r) * HD + s);
        }
        cp_commit();
    };

    prefetchKV(0, 0);
    prefetchKV(1, 1);

    // Q tile: 128 rows x 64 (plain loads overlap the cp.async prologue)
#pragma unroll
    for (int i = 0; i < 4; i++) {
        int c = tid + 256 * i;
        int r = c >> 3, s = (c & 7) * 8;
        *(uint4*)&Qs[r][s] = *(const uint4*)(Q + base + (size_t)(q0 + r) * HD + s);
    }
    __syncthreads();   // Qs visible

    unsigned qa[4][4];
#pragma unroll
    for (int t = 0; t < 4; t++)
        ldsm4(qa[t], s2u(&Qs[qr + (lane & 15)][t*16 + (lane >> 4) * 8]));

    float o[8][4] = {};
    float den0 = 0.0f, den1 = 0.0f;

    const int NT = SQ / 64;
    for (int kt = 0; kt < NT; kt++) {
        cp_wait_tail(kt + 1 < NT);
        __syncthreads();
        if (kt + 2 < NT) prefetchKV(kt + 2, (kt + 2) % 3);
        const int st = kt % 3;

        // QK^T: 16 q x 64 keys x 64 d
        float sc[8][4] = {};
#pragma unroll
        for (int t = 0; t < 4; t++) {
            const int kk = t * 16;
#pragma unroll
            for (int jp = 0; jp < 4; jp++) {
                unsigned kb[4];
                ldsm4(kb, s2u(&Ks[st][jp*16 + ((lane >> 4) << 3) + (lane & 7)]
                                       [kk + ((lane >> 3) & 1) * 8]));
                mma16816(sc[jp*2],     qa[t], kb[0], kb[1]);
                mma16816(sc[jp*2 + 1], qa[t], kb[2], kb[3]);
            }
        }

        // Yat transform (fast div) + denominator partials
#pragma unroll
        for (int j = 0; j < 8; j++) {
#pragma unroll
            for (int r = 0; r < 4; r++) {
                float dot = sc[j][r];
                float t1 = 1.0f + dot;
                sc[j][r] = __fdividef(t1 * t1, 1.1f - dot);
            }
            den0 += sc[j][0] + sc[j][1];
            den1 += sc[j][2] + sc[j][3];
        }

        // P fp16 A-fragments from C-fragment registers
        unsigned ph[4][4];
#pragma unroll
        for (int t = 0; t < 4; t++) {
            ph[t][0] = packh2(sc[2*t][0],   sc[2*t][1]);
            ph[t][1] = packh2(sc[2*t][2],   sc[2*t][3]);
            ph[t][2] = packh2(sc[2*t+1][0], sc[2*t+1][1]);
            ph[t][3] = packh2(sc[2*t+1][2], sc[2*t+1][3]);
        }

        // P @ V: 16 q x 64 d x 64 keys
#pragma unroll
        for (int t = 0; t < 4; t++) {
            const int kk = t * 16;
#pragma unroll
            for (int jp = 0; jp < 4; jp++) {
                unsigned vb[4];
                ldsm4t(vb, s2u(&Vs[st][kk + ((lane >> 3) & 1) * 8 + (lane & 7)]
                                        [jp*16 + (lane >> 4) * 8]));
                mma16816(o[jp*2],     ph[t], vb[0], vb[1]);
                mma16816(o[jp*2 + 1], ph[t], vb[2], vb[3]);
            }
        }
    }

    // Reduce denominators across tig lanes
    den0 += __shfl_xor_sync(0xffffffff, den0, 1);
    den0 += __shfl_xor_sync(0xffffffff, den0, 2);
    den1 += __shfl_xor_sync(0xffffffff, den1, 1);
    den1 += __shfl_xor_sync(0xffffffff, den1, 2);
    float inv0 = 1.0f / (den0 + 1e-6f);
    float inv1 = 1.0f / (den1 + 1e-6f);

    const size_t obase = (size_t)bb * SQ * EM + (size_t)h * HD;
    int r0 = q0 + qr + g, r1 = r0 + 8;
#pragma unroll
    for (int j = 0; j < 8; j++) {
        int col = j * 8 + tig * 2;
        *(__half2*)(ctx + obase + (size_t)r0 * EM + col) =
            __floats2half2_rn(o[j][0] * inv0, o[j][1] * inv0);
        *(__half2*)(ctx + obase + (size_t)r1 * EM + col) =
            __floats2half2_rn(o[j][2] * inv1, o[j][3] * inv1);
    }
}

// ---------------------------------------------------------------------------
extern "C" void kernel_launch(void* const* d_in, const int* in_sizes, int n_in,
                              void* d_out, int out_size)
{
    const float* x  = (const float*)d_in[0];
    const float* Wq = (const float*)d_in[1];
    const float* bq = (const float*)d_in[2];
    const float* Wk = (const float*)d_in[3];
    const float* bk = (const float*)d_in[4];
    const float* Wv = (const float*)d_in[5];
    const float* bv = (const float*)d_in[6];
    const float* Wo = (const float*)d_in[7];
    const float* bo = (const float*)d_in[8];
    float* out = (float*)d_out;

    __half *dXh, *dCh, *dQh, *dKh, *dVh;
    cudaGetSymbolAddress((void**)&dXh, g_Xh);
    cudaGetSymbolAddress((void**)&dCh, g_Ch);
    cudaGetSymbolAddress((void**)&dQh, g_Qh);
    cudaGetSymbolAddress((void**)&dKh, g_Kh);
    cudaGetSymbolAddress((void**)&dVh, g_Vh);

    const int M = NB * SQ;

    // Single fused fp32 -> fp16 staging pass (x + all 4 weights)
    f2h_all<<<4096, 256>>>(x, Wq, Wk, Wv, Wo);

    const int gemm_smem = 3*128*APAD*2 + 3*64*BPAD*2;   // 107,520 B
    cudaFuncSetAttribute(gemm_tc, cudaFuncAttributeMaxDynamicSharedMemorySize, gemm_smem);

    // Fused QKV (+ fused L2 norm on Q/K)
    gemm_tc<<<dim3(24, M / 128), 256, gemm_smem>>>(dXh, bq, bk, bv, nullptr, 1);

    const int attn_smem = (128*APAD + 6*64*APAD) * 2;   // 73,728 B
    cudaFuncSetAttribute(yat_attn2, cudaFuncAttributeMaxDynamicSharedMemorySize, attn_smem);
    yat_attn2<<<dim3(SQ / 128, NH, NB), 256, attn_smem>>>(dQh, dKh, dVh, dCh);

    // Output projection
    gemm_tc<<<dim3(8, M / 128), 256, gemm_smem>>>(dCh, bo, nullptr, nullptr, out, 0);
}

// round 11
// speedup vs baseline: 7.5033x; 1.0489x over previous
#include <cuda_runtime.h>
#include <cuda_fp16.h>
#include <cstdint>
#include <math.h>

#define NB 2
#define NH 16
#define HD 64
#define SQ 2048
#define EM 1024

// Scratch (device globals; runtime allocation is forbidden)
__device__ __align__(256) __half g_Xh[(size_t)NB*SQ*EM];
__device__ __align__(256) __half g_Wh[(size_t)4*EM*EM];   // Wq,Wk,Wv,Wo fp16
__device__ __align__(256) __half g_Qh[(size_t)NB*NH*SQ*HD];
__device__ __align__(256) __half g_Kh[(size_t)NB*NH*SQ*HD];
__device__ __align__(256) __half g_Vh[(size_t)NB*NH*SQ*HD];
__device__ __align__(256) __half g_Ch[(size_t)NB*SQ*EM];

// ---------------------------------------------------------------------------
__device__ __forceinline__ void mma16816(float c[4], const unsigned a[4],
                                         unsigned b0, unsigned b1)
{
    asm volatile(
        "mma.sync.aligned.m16n8k16.row.col.f32.f16.f16.f32 "
        "{%0,%1,%2,%3}, {%4,%5,%6,%7}, {%8,%9}, {%0,%1,%2,%3};\n"
        : "+f"(c[0]), "+f"(c[1]), "+f"(c[2]), "+f"(c[3])
        : "r"(a[0]), "r"(a[1]), "r"(a[2]), "r"(a[3]), "r"(b0), "r"(b1));
}
__device__ __forceinline__ unsigned packh2(float x, float y)
{
    __half2 h = __floats2half2_rn(x, y);
    return *(unsigned*)&h;
}
__device__ __forceinline__ uint32_t s2u(const void* p)
{
    return (uint32_t)__cvta_generic_to_shared(p);
}
__device__ __forceinline__ void ldsm4(unsigned r[4], uint32_t a)
{
    asm volatile("ldmatrix.sync.aligned.m8n8.x4.shared.b16 {%0,%1,%2,%3}, [%4];"
                 : "=r"(r[0]), "=r"(r[1]), "=r"(r[2]), "=r"(r[3]) : "r"(a));
}
__device__ __forceinline__ void ldsm4t(unsigned r[4], uint32_t a)
{
    asm volatile("ldmatrix.sync.aligned.m8n8.x4.trans.shared.b16 {%0,%1,%2,%3}, [%4];"
                 : "=r"(r[0]), "=r"(r[1]), "=r"(r[2]), "=r"(r[3]) : "r"(a));
}
__device__ __forceinline__ void cpa16(uint32_t d, const void* s)
{
    asm volatile("cp.async.ca.shared.global [%0], [%1], 16;" :: "r"(d), "l"(s));
}
__device__ __forceinline__ void cpa16cg(uint32_t d, const void* s)
{
    asm volatile("cp.async.cg.shared.global [%0], [%1], 16;" :: "r"(d), "l"(s));
}
__device__ __forceinline__ void cp_commit() { asm volatile("cp.async.commit_group;"); }
__device__ __forceinline__ void cp_wait_tail(bool more)
{
    if (more) asm volatile("cp.async.wait_group 1;");
    else      asm volatile("cp.async.wait_group 0;");
}
__device__ __forceinline__ void cp_wait0() { asm volatile("cp.async.wait_group 0;"); }

// ---------------------------------------------------------------------------
// Fused fp32->fp16: x (2M floats) + 4 weights (1M floats each), grid-stride.
// ---------------------------------------------------------------------------
#define X_F4   ((NB*SQ*EM)/4)
#define W_F4   ((EM*EM)/4)
#define TOT_F4 (X_F4 + 4*W_F4)

__global__ void f2h_all(const float* __restrict__ x,
                        const float* __restrict__ w0, const float* __restrict__ w1,
                        const float* __restrict__ w2, const float* __restrict__ w3)
{
    __half* dstX = g_Xh;
    __half* dstW = g_Wh;
    for (int i = blockIdx.x * blockDim.x + threadIdx.x; i < TOT_F4;
         i += gridDim.x * blockDim.x) {
        const float* src; __half* dst; int off;
        if (i < X_F4) { src = x; dst = dstX; off = i; }
        else {
            int j = i - X_F4;
            int w = j / W_F4;  off = j - w * W_F4;
            src = (w == 0) ? w0 : (w == 1) ? w1 : (w == 2) ? w2 : w3;
            dst = dstW + (size_t)w * (EM * EM);
        }
        float4 v = ((const float4*)src)[off];
        ((__half2*)dst)[off*2]   = __floats2half2_rn(v.x, v.y);
        ((__half2*)dst)[off*2+1] = __floats2half2_rn(v.z, v.w);
    }
}

// ---------------------------------------------------------------------------
// Tensor-core GEMM, 128x128 block, k-chunk 64.
// 2-stage cp.async.cg pipeline, ONE sync/iter (wait -> sync -> prefetch ->
// compute), 2 CTAs/SM; ldmatrix fragments double-buffered in registers
// across the 4 k-substeps to break the LDSM->HMMA dependency chain.
// qkv=1: fused QKV (grid.x = 24, wsel = bx>>3), L2-norm fused for Q/K,
//        writes fp16 scattered [B,H,S,D].  qkv=0: Wo, fp32 [M,N] + bias.
// ---------------------------------------------------------------------------
#define APAD 72
#define BPAD 136

__global__ __launch_bounds__(256, 2)
void gemm_tc(const __half* __restrict__ A,
             const float* __restrict__ bq, const float* __restrict__ bk,
             const float* __restrict__ bv, float* __restrict__ Cout, int qkv)
{
    extern __shared__ __half sm[];
    __half (*As)[128][APAD] = (__half(*)[128][APAD])sm;
    __half (*Bs)[64][BPAD]  = (__half(*)[64][BPAD])(sm + 2*128*APAD);

    int wsel, n0;
    if (qkv) { wsel = blockIdx.x >> 3; n0 = (blockIdx.x & 7) * 128; }
    else     { wsel = 3;               n0 = blockIdx.x * 128; }
    const int m0 = blockIdx.y * 128;
    const __half* W = g_Wh + (size_t)wsel * EM * EM;
    const float* bias = qkv ? (wsel == 0 ? bq : (wsel == 1 ? bk : bv)) : bq;

    const int tid = threadIdx.x;
    const int wid = tid >> 5, lane = tid & 31;
    const int g = lane >> 2, tig = lane & 3;
    const int wm = (wid >> 2) * 64, wn = (wid & 3) * 32;

    auto prefetch = [&](int kt, int st) {
        int k0 = kt * 64;
#pragma unroll
        for (int i = 0; i < 4; i++) {
            int c = tid + 256 * i;
            int r = c >> 3, s = (c & 7) * 8;
            cpa16cg(s2u(&As[st][r][s]), A + (size_t)(m0 + r) * EM + k0 + s);
        }
#pragma unroll
        for (int i = 0; i < 4; i++) {
            int c = tid + 256 * i;
            int r = c >> 4, s = (c & 15) * 8;
            cpa16cg(s2u(&Bs[st][r][s]), W + (size_t)(k0 + r) * EM + n0 + s);
        }
        cp_commit();
    };

    float c[4][4][4] = {};
    unsigned af[2][4][4], bf[2][2][4];

    auto loadf = [&](int st, int t, int buf) {
        const int kk = t * 16;
#pragma unroll
        for (int i = 0; i < 4; i++)
            ldsm4(af[buf][i], s2u(&As[st][wm + 16*i + (lane & 15)][kk + (lane >> 4) * 8]));
#pragma unroll
        for (int jp = 0; jp < 2; jp++)
            ldsm4t(bf[buf][jp], s2u(&Bs[st][kk + (lane & 15)][wn + jp*16 + (lane >> 4) * 8]));
    };

    prefetch(0, 0);
    const int NIT = EM / 64;   // 16
    for (int kt = 0; kt < NIT; kt++) {
        cp_wait0();
        __syncthreads();
        if (kt + 1 < NIT) prefetch(kt + 1, (kt + 1) & 1);
        const int st = kt & 1;

        loadf(st, 0, 0);
#pragma unroll
        for (int t = 0; t < 4; t++) {
            const int cur = t & 1;
            if (t < 3) loadf(st, t + 1, cur ^ 1);
#pragma unroll
            for (int i = 0; i < 4; i++)
#pragma unroll
                for (int j = 0; j < 4; j++)
                    mma16816(c[i][j], af[cur][i],
                             bf[cur][j >> 1][(j & 1) * 2],
                             bf[cur][j >> 1][(j & 1) * 2 + 1]);
        }
    }

    // ---- Epilogue: add bias in place ----
#pragma unroll
    for (int j = 0; j < 4; j++) {
        int col = n0 + wn + j * 8 + tig * 2;
        float bi0 = bias[col], bi1 = bias[col + 1];
#pragma unroll
        for (int i = 0; i < 4; i++) {
            c[i][j][0] += bi0; c[i][j][1] += bi1;
            c[i][j][2] += bi0; c[i][j][3] += bi1;
        }
    }

    // ---- Fused L2 norm for Q/K (per row within each 64-col head) ----
    if (qkv && wsel < 2) {
        float sq0[4], sq1[4];
#pragma unroll
        for (int i = 0; i < 4; i++) {
            sq0[i] = 0.0f; sq1[i] = 0.0f;
#pragma unroll
            for (int j = 0; j < 4; j++) {
                sq0[i] += c[i][j][0]*c[i][j][0] + c[i][j][1]*c[i][j][1];
                sq1[i] += c[i][j][2]*c[i][j][2] + c[i][j][3]*c[i][j][3];
            }
        }
#pragma unroll
        for (int i = 0; i < 4; i++) {
            sq0[i] += __shfl_xor_sync(0xffffffffu, sq0[i], 1);
            sq0[i] += __shfl_xor_sync(0xffffffffu, sq0[i], 2);
            sq1[i] += __shfl_xor_sync(0xffffffffu, sq1[i], 1);
            sq1[i] += __shfl_xor_sync(0xffffffffu, sq1[i], 2);
        }
        float* ss = (float*)sm;   // [8 warps][64 rows] = 2 KB, reuse tile smem
        __syncthreads();          // everyone out of the mainloop smem
        if (tig == 0) {
#pragma unroll
            for (int i = 0; i < 4; i++) {
                ss[wid*64 + 16*i + g]     = sq0[i];
                ss[wid*64 + 16*i + g + 8] = sq1[i];
            }
        }
        __syncthreads();
        const int pw = wid ^ 1;   // partner warp covering the other 32 cols of head
#pragma unroll
        for (int i = 0; i < 4; i++) {
            float t0 = ss[wid*64 + 16*i + g]     + ss[pw*64 + 16*i + g];
            float t1 = ss[wid*64 + 16*i + g + 8] + ss[pw*64 + 16*i + g + 8];
            float s0 = 1.0f / (sqrtf(t0) + 1e-8f);
            float s1 = 1.0f / (sqrtf(t1) + 1e-8f);
#pragma unroll
            for (int j = 0; j < 4; j++) {
                c[i][j][0] *= s0; c[i][j][1] *= s0;
                c[i][j][2] *= s1; c[i][j][3] *= s1;
            }
        }
    }

    // ---- Write out ----
#pragma unroll
    for (int j = 0; j < 4; j++) {
        int col = n0 + wn + j * 8 + tig * 2;
#pragma unroll
        for (int i = 0; i < 4; i++) {
            int r0 = m0 + wm + 16 * i + g, r1 = r0 + 8;
            if (!qkv) {
                *(float2*)(Cout + (size_t)r0 * EM + col) = make_float2(c[i][j][0], c[i][j][1]);
                *(float2*)(Cout + (size_t)r1 * EM + col) = make_float2(c[i][j][2], c[i][j][3]);
            } else {
                __half* Out = wsel == 0 ? g_Qh : (wsel == 1 ? g_Kh : g_Vh);
                int hh = col >> 6, d = col & 63;
                int bb0 = r0 >> 11, s0 = r0 & 2047;
                int bb1 = r1 >> 11, s1 = r1 & 2047;
                *(__half2*)(Out + (((size_t)(bb0*NH + hh) * SQ + s0) * HD) + d) =
                    __floats2half2_rn(c[i][j][0], c[i][j][1]);
                *(__half2*)(Out + (((size_t)(bb1*NH + hh) * SQ + s1) * HD) + d) =
                    __floats2half2_rn(c[i][j][2], c[i][j][3]);
            }
        }
    }
}

// ---------------------------------------------------------------------------
// Yat attention, tensor cores. Block = (b, h, 128 queries), 8 warps.
// K/V tiles (64 keys) 3-stage cp.async pipeline, ONE sync per tile.
// Yat transform uses fast division (__fdividef; den in [0.1, 2.1]).
// ---------------------------------------------------------------------------
__global__ __launch_bounds__(256)
void yat_attn2(const __half* __restrict__ Q, const __half* __restrict__ K,
               const __half* __restrict__ V, __half* __restrict__ ctx)
{
    extern __shared__ __half sm2[];
    __half (*Qs)[APAD]     = (__half(*)[APAD])sm2;                      // [128][72]
    __half (*Ks)[64][APAD] = (__half(*)[64][APAD])(sm2 + 128*APAD);     // [3][64][72]
    __half (*Vs)[64][APAD] = (__half(*)[64][APAD])(sm2 + 128*APAD + 3*64*APAD);

    const int q0 = blockIdx.x * 128;
    const int h  = blockIdx.y;
    const int bb = blockIdx.z;
    const size_t base = ((size_t)bb * NH + h) * SQ * HD;
    const int tid = threadIdx.x;
    const int wid = tid >> 5, lane = tid & 31;
    const int g = lane >> 2, tig = lane & 3;
    const int qr = wid * 16;

    auto prefetchKV = [&](int kt, int st) {
        int k0 = kt * 64;
#pragma unroll
        for (int i = 0; i < 2; i++) {
            int c = tid + 256 * i;
            int r = c >> 3, s = (c & 7) * 8;
            cpa16(s2u(&Ks[st][r][s]), K + base + (size_t)(k0 + r) * HD + s);
            cpa16(s2u(&Vs[st][r][s]), V + base + (size_t)(k0 + r) * HD + s);
        }
        cp_commit();
    };

    prefetchKV(0, 0);
    prefetchKV(1, 1);

#pragma unroll
    for (int i = 0; i < 4; i++) {
        int c = tid + 256 * i;
        int r = c >> 3, s = (c & 7) * 8;
        *(uint4*)&Qs[r][s] = *(const uint4*)(Q + base + (size_t)(q0 + r) * HD + s);
    }
    __syncthreads();

    unsigned qa[4][4];
#pragma unroll
    for (int t = 0; t < 4; t++)
        ldsm4(qa[t], s2u(&Qs[qr + (lane & 15)][t*16 + (lane >> 4) * 8]));

    float o[8][4] = {};
    float den0 = 0.0f, den1 = 0.0f;

    const int NT = SQ / 64;
    for (int kt = 0; kt < NT; kt++) {
        cp_wait_tail(kt + 1 < NT);
        __syncthreads();
        if (kt + 2 < NT) prefetchKV(kt + 2, (kt + 2) % 3);
        const int st = kt % 3;

        float sc[8][4] = {};
#pragma unroll
        for (int t = 0; t < 4; t++) {
            const int kk = t * 16;
#pragma unroll
            for (int jp = 0; jp < 4; jp++) {
                unsigned kb[4];
                ldsm4(kb, s2u(&Ks[st][jp*16 + ((lane >> 4) << 3) + (lane & 7)]
                                       [kk + ((lane >> 3) & 1) * 8]));
                mma16816(sc[jp*2],     qa[t], kb[0], kb[1]);
                mma16816(sc[jp*2 + 1], qa[t], kb[2], kb[3]);
            }
        }

#pragma unroll
        for (int j = 0; j < 8; j++) {
#pragma unroll
            for (int r = 0; r < 4; r++) {
                float dot = sc[j][r];
                float t1 = 1.0f + dot;
                sc[j][r] = __fdividef(t1 * t1, 1.1f - dot);
            }
            den0 += sc[j][0] + sc[j][1];
            den1 += sc[j][2] + sc[j][3];
        }

        unsigned pf[4][4];
#pragma unroll
        for (int t = 0; t < 4; t++) {
            pf[t][0] = packh2(sc[2*t][0],   sc[2*t][1]);
            pf[t][1] = packh2(sc[2*t][2],   sc[2*t][3]);
            pf[t][2] = packh2(sc[2*t+1][0], sc[2*t+1][1]);
            pf[t][3] = packh2(sc[2*t+1][2], sc[2*t+1][3]);
        }

#pragma unroll
        for (int t = 0; t < 4; t++) {
            const int kk = t * 16;
#pragma unroll
            for (int jp = 0; jp < 4; jp++) {
                unsigned vb[4];
                ldsm4t(vb, s2u(&Vs[st][kk + ((lane >> 3) & 1) * 8 + (lane & 7)]
                                        [jp*16 + (lane >> 4) * 8]));
                mma16816(o[jp*2],     pf[t], vb[0], vb[1]);
                mma16816(o[jp*2 + 1], pf[t], vb[2], vb[3]);
            }
        }
    }

    den0 += __shfl_xor_sync(0xffffffff, den0, 1);
    den0 += __shfl_xor_sync(0xffffffff, den0, 2);
    den1 += __shfl_xor_sync(0xffffffff, den1, 1);
    den1 += __shfl_xor_sync(0xffffffff, den1, 2);
    float inv0 = 1.0f / (den0 + 1e-6f);
    float inv1 = 1.0f / (den1 + 1e-6f);

    const size_t obase = (size_t)bb * SQ * EM + (size_t)h * HD;
    int r0 = q0 + qr + g, r1 = r0 + 8;
#pragma unroll
    for (int j = 0; j < 8; j++) {
        int col = j * 8 + tig * 2;
        *(__half2*)(ctx + obase + (size_t)r0 * EM + col) =
            __floats2half2_rn(o[j][0] * inv0, o[j][1] * inv0);
        *(__half2*)(ctx + obase + (size_t)r1 * EM + col) =
            __floats2half2_rn(o[j][2] * inv1, o[j][3] * inv1);
    }
}

// ---------------------------------------------------------------------------
extern "C" void kernel_launch(void* const* d_in, const int* in_sizes, int n_in,
                              void* d_out, int out_size)
{
    const float* x  = (const float*)d_in[0];
    const float* Wq = (const float*)d_in[1];
    const float* bq = (const float*)d_in[2];
    const float* Wk = (const float*)d_in[3];
    const float* bk = (const float*)d_in[4];
    const float* Wv = (const float*)d_in[5];
    const float* bv = (const float*)d_in[6];
    const float* Wo = (const float*)d_in[7];
    const float* bo = (const float*)d_in[8];
    float* out = (float*)d_out;

    __half *dXh, *dCh, *dQh, *dKh, *dVh;
    cudaGetSymbolAddress((void**)&dXh, g_Xh);
    cudaGetSymbolAddress((void**)&dCh, g_Ch);
    cudaGetSymbolAddress((void**)&dQh, g_Qh);
    cudaGetSymbolAddress((void**)&dKh, g_Kh);
    cudaGetSymbolAddress((void**)&dVh, g_Vh);

    const int M = NB * SQ;

    // Single fused fp32 -> fp16 staging pass (x + all 4 weights)
    f2h_all<<<4096, 256>>>(x, Wq, Wk, Wv, Wo);

    const int gemm_smem = 2*128*APAD*2 + 2*64*BPAD*2;   // 71,680 B -> 2 CTAs/SM
    cudaFuncSetAttribute(gemm_tc, cudaFuncAttributeMaxDynamicSharedMemorySize, gemm_smem);

    // Fused QKV (+ fused L2 norm on Q/K)
    gemm_tc<<<dim3(24, M / 128), 256, gemm_smem>>>(dXh, bq, bk, bv, nullptr, 1);

    const int attn_smem = (128*APAD + 6*64*APAD) * 2;   // 73,728 B
    cudaFuncSetAttribute(yat_attn2, cudaFuncAttributeMaxDynamicSharedMemorySize, attn_smem);
    yat_attn2<<<dim3(SQ / 128, NH, NB), 256, attn_smem>>>(dQh, dKh, dVh, dCh);

    // Output projection
    gemm_tc<<<dim3(8, M / 128), 256, gemm_smem>>>(dCh, bo, nullptr, nullptr, out, 0);
}

// round 14
// speedup vs baseline: 7.5156x; 1.0016x over previous
#include <cuda_runtime.h>
#include <cuda_fp16.h>
#include <cstdint>
#include <math.h>

#define NB 2
#define NH 16
#define HD 64
#define SQ 2048
#define EM 1024

// Scratch (device globals; runtime allocation is forbidden)
__device__ __align__(256) __half g_Xh[(size_t)NB*SQ*EM];
__device__ __align__(256) __half g_Wh[(size_t)4*EM*EM];   // Wq,Wk,Wv,Wo fp16
__device__ __align__(256) __half g_Qh[(size_t)NB*NH*SQ*HD];
__device__ __align__(256) __half g_Kh[(size_t)NB*NH*SQ*HD];
__device__ __align__(256) __half g_Vh[(size_t)NB*NH*SQ*HD];
__device__ __align__(256) __half g_Ch[(size_t)NB*SQ*EM];

// ---------------------------------------------------------------------------
__device__ __forceinline__ void mma16816(float c[4], const unsigned a[4],
                                         unsigned b0, unsigned b1)
{
    asm volatile(
        "mma.sync.aligned.m16n8k16.row.col.f32.f16.f16.f32 "
        "{%0,%1,%2,%3}, {%4,%5,%6,%7}, {%8,%9}, {%0,%1,%2,%3};\n"
        : "+f"(c[0]), "+f"(c[1]), "+f"(c[2]), "+f"(c[3])
        : "r"(a[0]), "r"(a[1]), "r"(a[2]), "r"(a[3]), "r"(b0), "r"(b1));
}
__device__ __forceinline__ unsigned packh2(float x, float y)
{
    __half2 h = __floats2half2_rn(x, y);
    return *(unsigned*)&h;
}
__device__ __forceinline__ uint32_t s2u(const void* p)
{
    return (uint32_t)__cvta_generic_to_shared(p);
}
__device__ __forceinline__ void ldsm4(unsigned r[4], uint32_t a)
{
    asm volatile("ldmatrix.sync.aligned.m8n8.x4.shared.b16 {%0,%1,%2,%3}, [%4];"
                 : "=r"(r[0]), "=r"(r[1]), "=r"(r[2]), "=r"(r[3]) : "r"(a));
}
__device__ __forceinline__ void ldsm4t(unsigned r[4], uint32_t a)
{
    asm volatile("ldmatrix.sync.aligned.m8n8.x4.trans.shared.b16 {%0,%1,%2,%3}, [%4];"
                 : "=r"(r[0]), "=r"(r[1]), "=r"(r[2]), "=r"(r[3]) : "r"(a));
}
__device__ __forceinline__ void cpa16(uint32_t d, const void* s)
{
    asm volatile("cp.async.ca.shared.global [%0], [%1], 16;" :: "r"(d), "l"(s));
}
__device__ __forceinline__ void cpa16cg(uint32_t d, const void* s)
{
    asm volatile("cp.async.cg.shared.global [%0], [%1], 16;" :: "r"(d), "l"(s));
}
__device__ __forceinline__ void cp_commit() { asm volatile("cp.async.commit_group;"); }
__device__ __forceinline__ void cp_wait_tail(bool more)
{
    if (more) asm volatile("cp.async.wait_group 1;");
    else      asm volatile("cp.async.wait_group 0;");
}
__device__ __forceinline__ void cp_wait0() { asm volatile("cp.async.wait_group 0;"); }

// ---------------------------------------------------------------------------
// Fused fp32->fp16: x (2M floats) + 4 weights (1M floats each), grid-stride.
// ---------------------------------------------------------------------------
#define X_F4   ((NB*SQ*EM)/4)
#define W_F4   ((EM*EM)/4)
#define TOT_F4 (X_F4 + 4*W_F4)

__global__ void f2h_all(const float* __restrict__ x,
                        const float* __restrict__ w0, const float* __restrict__ w1,
                        const float* __restrict__ w2, const float* __restrict__ w3)
{
    __half* dstX = g_Xh;
    __half* dstW = g_Wh;
    for (int i = blockIdx.x * blockDim.x + threadIdx.x; i < TOT_F4;
         i += gridDim.x * blockDim.x) {
        const float* src; __half* dst; int off;
        if (i < X_F4) { src = x; dst = dstX; off = i; }
        else {
            int j = i - X_F4;
            int w = j / W_F4;  off = j - w * W_F4;
            src = (w == 0) ? w0 : (w == 1) ? w1 : (w == 2) ? w2 : w3;
            dst = dstW + (size_t)w * (EM * EM);
        }
        float4 v = ((const float4*)src)[off];
        ((__half2*)dst)[off*2]   = __floats2half2_rn(v.x, v.y);
        ((__half2*)dst)[off*2+1] = __floats2half2_rn(v.z, v.w);
    }
}

// ---------------------------------------------------------------------------
// Tensor-core GEMM (unchanged from R11 pass): 128x128 block, k-chunk 64,
// 2-stage cp.async.cg, one sync/iter, register-double-buffered fragments.
// ---------------------------------------------------------------------------
#define APAD 72
#define BPAD 136

__global__ __launch_bounds__(256, 2)
void gemm_tc(const __half* __restrict__ A,
             const float* __restrict__ bq, const float* __restrict__ bk,
             const float* __restrict__ bv, float* __restrict__ Cout, int qkv)
{
    extern __shared__ __half sm[];
    __half (*As)[128][APAD] = (__half(*)[128][APAD])sm;
    __half (*Bs)[64][BPAD]  = (__half(*)[64][BPAD])(sm + 2*128*APAD);

    int wsel, n0;
    if (qkv) { wsel = blockIdx.x >> 3; n0 = (blockIdx.x & 7) * 128; }
    else     { wsel = 3;               n0 = blockIdx.x * 128; }
    const int m0 = blockIdx.y * 128;
    const __half* W = g_Wh + (size_t)wsel * EM * EM;
    const float* bias = qkv ? (wsel == 0 ? bq : (wsel == 1 ? bk : bv)) : bq;

    const int tid = threadIdx.x;
    const int wid = tid >> 5, lane = tid & 31;
    const int g = lane >> 2, tig = lane & 3;
    const int wm = (wid >> 2) * 64, wn = (wid & 3) * 32;

    auto prefetch = [&](int kt, int st) {
        int k0 = kt * 64;
#pragma unroll
        for (int i = 0; i < 4; i++) {
            int c = tid + 256 * i;
            int r = c >> 3, s = (c & 7) * 8;
            cpa16cg(s2u(&As[st][r][s]), A + (size_t)(m0 + r) * EM + k0 + s);
        }
#pragma unroll
        for (int i = 0; i < 4; i++) {
            int c = tid + 256 * i;
            int r = c >> 4, s = (c & 15) * 8;
            cpa16cg(s2u(&Bs[st][r][s]), W + (size_t)(k0 + r) * EM + n0 + s);
        }
        cp_commit();
    };

    float c[4][4][4] = {};
    unsigned af[2][4][4], bf[2][2][4];

    auto loadf = [&](int st, int t, int buf) {
        const int kk = t * 16;
#pragma unroll
        for (int i = 0; i < 4; i++)
            ldsm4(af[buf][i], s2u(&As[st][wm + 16*i + (lane & 15)][kk + (lane >> 4) * 8]));
#pragma unroll
        for (int jp = 0; jp < 2; jp++)
            ldsm4t(bf[buf][jp], s2u(&Bs[st][kk + (lane & 15)][wn + jp*16 + (lane >> 4) * 8]));
    };

    prefetch(0, 0);
    const int NIT = EM / 64;   // 16
    for (int kt = 0; kt < NIT; kt++) {
        cp_wait0();
        __syncthreads();
        if (kt + 1 < NIT) prefetch(kt + 1, (kt + 1) & 1);
        const int st = kt & 1;

        loadf(st, 0, 0);
#pragma unroll
        for (int t = 0; t < 4; t++) {
            const int cur = t & 1;
            if (t < 3) loadf(st, t + 1, cur ^ 1);
#pragma unroll
            for (int i = 0; i < 4; i++)
#pragma unroll
                for (int j = 0; j < 4; j++)
                    mma16816(c[i][j], af[cur][i],
                             bf[cur][j >> 1][(j & 1) * 2],
                             bf[cur][j >> 1][(j & 1) * 2 + 1]);
        }
    }

    // ---- Epilogue: add bias in place ----
#pragma unroll
    for (int j = 0; j < 4; j++) {
        int col = n0 + wn + j * 8 + tig * 2;
        float bi0 = bias[col], bi1 = bias[col + 1];
#pragma unroll
        for (int i = 0; i < 4; i++) {
            c[i][j][0] += bi0; c[i][j][1] += bi1;
            c[i][j][2] += bi0; c[i][j][3] += bi1;
        }
    }

    // ---- Fused L2 norm for Q/K (per row within each 64-col head) ----
    if (qkv && wsel < 2) {
        float sq0[4], sq1[4];
#pragma unroll
        for (int i = 0; i < 4; i++) {
            sq0[i] = 0.0f; sq1[i] = 0.0f;
#pragma unroll
            for (int j = 0; j < 4; j++) {
                sq0[i] += c[i][j][0]*c[i][j][0] + c[i][j][1]*c[i][j][1];
                sq1[i] += c[i][j][2]*c[i][j][2] + c[i][j][3]*c[i][j][3];
            }
        }
#pragma unroll
        for (int i = 0; i < 4; i++) {
            sq0[i] += __shfl_xor_sync(0xffffffffu, sq0[i], 1);
            sq0[i] += __shfl_xor_sync(0xffffffffu, sq0[i], 2);
            sq1[i] += __shfl_xor_sync(0xffffffffu, sq1[i], 1);
            sq1[i] += __shfl_xor_sync(0xffffffffu, sq1[i], 2);
        }
        float* ss = (float*)sm;   // [8 warps][64 rows] = 2 KB, reuse tile smem
        __syncthreads();
        if (tig == 0) {
#pragma unroll
            for (int i = 0; i < 4; i++) {
                ss[wid*64 + 16*i + g]     = sq0[i];
                ss[wid*64 + 16*i + g + 8] = sq1[i];
            }
        }
        __syncthreads();
        const int pw = wid ^ 1;
#pragma unroll
        for (int i = 0; i < 4; i++) {
            float t0 = ss[wid*64 + 16*i + g]     + ss[pw*64 + 16*i + g];
            float t1 = ss[wid*64 + 16*i + g + 8] + ss[pw*64 + 16*i + g + 8];
            float s0 = 1.0f / (sqrtf(t0) + 1e-8f);
            float s1 = 1.0f / (sqrtf(t1) + 1e-8f);
#pragma unroll
            for (int j = 0; j < 4; j++) {
                c[i][j][0] *= s0; c[i][j][1] *= s0;
                c[i][j][2] *= s1; c[i][j][3] *= s1;
            }
        }
    }

    // ---- Write out ----
#pragma unroll
    for (int j = 0; j < 4; j++) {
        int col = n0 + wn + j * 8 + tig * 2;
#pragma unroll
        for (int i = 0; i < 4; i++) {
            int r0 = m0 + wm + 16 * i + g, r1 = r0 + 8;
            if (!qkv) {
                *(float2*)(Cout + (size_t)r0 * EM + col) = make_float2(c[i][j][0], c[i][j][1]);
                *(float2*)(Cout + (size_t)r1 * EM + col) = make_float2(c[i][j][2], c[i][j][3]);
            } else {
                __half* Out = wsel == 0 ? g_Qh : (wsel == 1 ? g_Kh : g_Vh);
                int hh = col >> 6, d = col & 63;
                int bb0 = r0 >> 11, s0 = r0 & 2047;
                int bb1 = r1 >> 11, s1 = r1 & 2047;
                *(__half2*)(Out + (((size_t)(bb0*NH + hh) * SQ + s0) * HD) + d) =
                    __floats2half2_rn(c[i][j][0], c[i][j][1]);
                *(__half2*)(Out + (((size_t)(bb1*NH + hh) * SQ + s1) * HD) + d) =
                    __floats2half2_rn(c[i][j][2], c[i][j][3]);
            }
        }
    }
}

// ---------------------------------------------------------------------------
// Yat attention. Block = (b, h, 256 queries), 8 warps, 32 q per warp
// (two 16-row m-subtiles) -> K/V fragments reused 2x: 64 MMA per 16 LDSM.
// K/V 64-key tiles, 3-stage cp.async, one sync per tile.
// ---------------------------------------------------------------------------
__global__ __launch_bounds__(256)
void yat_attn3(const __half* __restrict__ Q, const __half* __restrict__ K,
               const __half* __restrict__ V, __half* __restrict__ ctx)
{
    extern __shared__ __half sm2[];
    __half (*Qs)[APAD]     = (__half(*)[APAD])sm2;                      // [256][72]
    __half (*Ks)[64][APAD] = (__half(*)[64][APAD])(sm2 + 256*APAD);     // [3][64][72]
    __half (*Vs)[64][APAD] = (__half(*)[64][APAD])(sm2 + 256*APAD + 3*64*APAD);

    const int q0 = blockIdx.x * 256;
    const int h  = blockIdx.y;
    const int bb = blockIdx.z;
    const size_t base = ((size_t)bb * NH + h) * SQ * HD;
    const int tid = threadIdx.x;
    const int wid = tid >> 5, lane = tid & 31;
    const int g = lane >> 2, tig = lane & 3;
    const int qr = wid * 32;

    auto prefetchKV = [&](int kt, int st) {
        int k0 = kt * 64;
#pragma unroll
        for (int i = 0; i < 2; i++) {
            int c = tid + 256 * i;
            int r = c >> 3, s = (c & 7) * 8;
            cpa16(s2u(&Ks[st][r][s]), K + base + (size_t)(k0 + r) * HD + s);
            cpa16(s2u(&Vs[st][r][s]), V + base + (size_t)(k0 + r) * HD + s);
        }
        cp_commit();
    };

    prefetchKV(0, 0);
    prefetchKV(1, 1);

    // Q tile: 256 rows x 64 halves = 2048 16B-chunks, 8 per thread
#pragma unroll
    for (int i = 0; i < 8; i++) {
        int c = tid + 256 * i;
        int r = c >> 3, s = (c & 7) * 8;
        *(uint4*)&Qs[r][s] = *(const uint4*)(Q + base + (size_t)(q0 + r) * HD + s);
    }
    __syncthreads();

    unsigned qa[2][4][4];
#pragma unroll
    for (int s = 0; s < 2; s++)
#pragma unroll
        for (int t = 0; t < 4; t++)
            ldsm4(qa[s][t], s2u(&Qs[qr + s*16 + (lane & 15)][t*16 + (lane >> 4) * 8]));

    float o[2][8][4] = {};
    float den[2][2] = {};

    const int NT = SQ / 64;
    for (int kt = 0; kt < NT; kt++) {
        cp_wait_tail(kt + 1 < NT);
        __syncthreads();
        if (kt + 2 < NT) prefetchKV(kt + 2, (kt + 2) % 3);
        const int st = kt % 3;

        // QK^T: 32 q x 64 keys x 64 d; kb reused across both m-subtiles
        float sc[2][8][4] = {};
#pragma unroll
        for (int t = 0; t < 4; t++) {
            const int kk = t * 16;
#pragma unroll
            for (int jp = 0; jp < 4; jp++) {
                unsigned kb[4];
                ldsm4(kb, s2u(&Ks[st][jp*16 + ((lane >> 4) << 3) + (lane & 7)]
                                       [kk + ((lane >> 3) & 1) * 8]));
#pragma unroll
                for (int s = 0; s < 2; s++) {
                    mma16816(sc[s][jp*2],     qa[s][t], kb[0], kb[1]);
                    mma16816(sc[s][jp*2 + 1], qa[s][t], kb[2], kb[3]);
                }
            }
        }

        // Yat transform (fast div) + denominator partials
        unsigned pf[2][4][4];
#pragma unroll
        for (int s = 0; s < 2; s++) {
#pragma unroll
            for (int j = 0; j < 8; j++) {
#pragma unroll
                for (int r = 0; r < 4; r++) {
                    float dot = sc[s][j][r];
                    float t1 = 1.0f + dot;
                    sc[s][j][r] = __fdividef(t1 * t1, 1.1f - dot);
                }
                den[s][0] += sc[s][j][0] + sc[s][j][1];
                den[s][1] += sc[s][j][2] + sc[s][j][3];
            }
#pragma unroll
            for (int t = 0; t < 4; t++) {
                pf[s][t][0] = packh2(sc[s][2*t][0],   sc[s][2*t][1]);
                pf[s][t][1] = packh2(sc[s][2*t][2],   sc[s][2*t][3]);
                pf[s][t][2] = packh2(sc[s][2*t+1][0], sc[s][2*t+1][1]);
                pf[s][t][3] = packh2(sc[s][2*t+1][2], sc[s][2*t+1][3]);
            }
        }

        // P @ V: 32 q x 64 d x 64 keys; vb reused across both m-subtiles
#pragma unroll
        for (int t = 0; t < 4; t++) {
            const int kk = t * 16;
#pragma unroll
            for (int jp = 0; jp < 4; jp++) {
                unsigned vb[4];
                ldsm4t(vb, s2u(&Vs[st][kk + ((lane >> 3) & 1) * 8 + (lane & 7)]
                                        [jp*16 + (lane >> 4) * 8]));
#pragma unroll
                for (int s = 0; s < 2; s++) {
                    mma16816(o[s][jp*2],     pf[s][t], vb[0], vb[1]);
                    mma16816(o[s][jp*2 + 1], pf[s][t], vb[2], vb[3]);
                }
            }
        }
    }

    // Reduce denominators across tig lanes, write out
    const size_t obase = (size_t)bb * SQ * EM + (size_t)h * HD;
#pragma unroll
    for (int s = 0; s < 2; s++) {
        float d0 = den[s][0], d1 = den[s][1];
        d0 += __shfl_xor_sync(0xffffffff, d0, 1);
        d0 += __shfl_xor_sync(0xffffffff, d0, 2);
        d1 += __shfl_xor_sync(0xffffffff, d1, 1);
        d1 += __shfl_xor_sync(0xffffffff, d1, 2);
        float inv0 = 1.0f / (d0 + 1e-6f);
        float inv1 = 1.0f / (d1 + 1e-6f);
        int r0 = q0 + qr + s*16 + g, r1 = r0 + 8;
#pragma unroll
        for (int j = 0; j < 8; j++) {
            int col = j * 8 + tig * 2;
            *(__half2*)(ctx + obase + (size_t)r0 * EM + col) =
                __floats2half2_rn(o[s][j][0] * inv0, o[s][j][1] * inv0);
            *(__half2*)(ctx + obase + (size_t)r1 * EM + col) =
                __floats2half2_rn(o[s][j][2] * inv1, o[s][j][3] * inv1);
        }
    }
}

// ---------------------------------------------------------------------------
extern "C" void kernel_launch(void* const* d_in, const int* in_sizes, int n_in,
                              void* d_out, int out_size)
{
    const float* x  = (const float*)d_in[0];
    const float* Wq = (const float*)d_in[1];
    const float* bq = (const float*)d_in[2];
    const float* Wk = (const float*)d_in[3];
    const float* bk = (const float*)d_in[4];
    const float* Wv = (const float*)d_in[5];
    const float* bv = (const float*)d_in[6];
    const float* Wo = (const float*)d_in[7];
    const float* bo = (const float*)d_in[8];
    float* out = (float*)d_out;

    __half *dXh, *dCh, *dQh, *dKh, *dVh;
    cudaGetSymbolAddress((void**)&dXh, g_Xh);
    cudaGetSymbolAddress((void**)&dCh, g_Ch);
    cudaGetSymbolAddress((void**)&dQh, g_Qh);
    cudaGetSymbolAddress((void**)&dKh, g_Kh);
    cudaGetSymbolAddress((void**)&dVh, g_Vh);

    const int M = NB * SQ;

    // Single fused fp32 -> fp16 staging pass (x + all 4 weights)
    f2h_all<<<4096, 256>>>(x, Wq, Wk, Wv, Wo);

    const int gemm_smem = 2*128*APAD*2 + 2*64*BPAD*2;   // 71,680 B -> 2 CTAs/SM
    cudaFuncSetAttribute(gemm_tc, cudaFuncAttributeMaxDynamicSharedMemorySize, gemm_smem);

    // Fused QKV (+ fused L2 norm on Q/K)
    gemm_tc<<<dim3(24, M / 128), 256, gemm_smem>>>(dXh, bq, bk, bv, nullptr, 1);

    const int attn_smem = (256*APAD + 6*64*APAD) * 2;   // 92,160 B
    cudaFuncSetAttribute(yat_attn3, cudaFuncAttributeMaxDynamicSharedMemorySize, attn_smem);
    yat_attn3<<<dim3(SQ / 256, NH, NB), 256, attn_smem>>>(dQh, dKh, dVh, dCh);

    // Output projection
    gemm_tc<<<dim3(8, M / 128), 256, gemm_smem>>>(dCh, bo, nullptr, nullptr, out, 0);
}